// round 13
// baseline (speedup 1.0000x reference)
#include <cuda_runtime.h>
#include <cstdint>
#include <math.h>

#define BATCH    256
#define SEQL     512
#define INDIM    64
#define UNITS    256
#define OUTSTEPS 64
#define OUTDIMS  32
#define G4       1024   // 4 * UNITS
#define NCTA_REC 128
#define HP       264    // hT row pitch (floats)
#define RP       72     // red row pitch
#define ZAP      20     // ZX gemm A smem pitch
#define ZBP      72     // B smem pitch (ZX + conv)
#define CAP      68     // conv A smem pitch

typedef unsigned long long ull;

// ---------------- scratch (static device globals; no allocation) ----------------
__device__ float d_X[BATCH * SEQL * UNITS];            // conv output
__device__ float d_ZX[(size_t)SEQL * BATCH * G4];      // x@W + b, [t][b][1024]
__device__ float d_HSEQ[BATCH * SEQL * UNITS];         // encoder hidden seq
__device__ float d_FSEQ[BATCH * OUTSTEPS * UNITS];     // decoder hidden seq
__device__ float d_HX[2][BATCH * UNITS];               // ping-pong h, tf32 bits
__device__ unsigned g_cnt2[16][32];                     // per-group barrier (padded lines)
__device__ unsigned g_gen2[16][32];                     // monotonic round counters

// ---------------- f32x2 helpers (backcast) ----------------
__device__ __forceinline__ ull pk2(float lo, float hi) {
    ull r; asm("mov.b64 %0, {%1, %2};" : "=l"(r) : "f"(lo), "f"(hi)); return r;
}
__device__ __forceinline__ void upk2(ull v, float& lo, float& hi) {
    asm("mov.b64 {%0, %1}, %2;" : "=f"(lo), "=f"(hi) : "l"(v));
}
__device__ __forceinline__ void ffma2(ull& d, ull a, ull b) {
    asm("fma.rn.f32x2 %0, %1, %2, %0;" : "+l"(d) : "l"(a), "l"(b));
}

// tf32 + mma helpers
__device__ __forceinline__ uint32_t to_tf32(float x) {
    uint32_t r; asm("cvt.rna.tf32.f32 %0, %1;" : "=r"(r) : "f"(x)); return r;
}
__device__ __forceinline__ void mma_tf32(float* c,
    uint32_t a0, uint32_t a1, uint32_t a2, uint32_t a3, uint32_t b0, uint32_t b1)
{
    asm("mma.sync.aligned.m16n8k8.row.col.f32.tf32.tf32.f32 "
        "{%0,%1,%2,%3}, {%4,%5,%6,%7}, {%8,%9}, {%0,%1,%2,%3};"
        : "+f"(c[0]), "+f"(c[1]), "+f"(c[2]), "+f"(c[3])
        : "r"(a0), "r"(a1), "r"(a2), "r"(a3), "r"(b0), "r"(b1));
}

// fast, overflow-safe gate functions
__device__ __forceinline__ float fast_sigmoid(float x) {
    return __fdividef(1.f, 1.f + __expf(-x));
}
__device__ __forceinline__ float fast_tanh(float x) {
    float e = __expf(-2.f * fabsf(x));
    float t = __fdividef(1.f - e, 1.f + e);
    return copysignf(t, x);
}

// ---------------- conv1d 'same' (K=5) + bias + relu via tf32 MMA ----------------
__global__ __launch_bounds__(256) void conv_tf32(
    const float* __restrict__ in, const float* __restrict__ ck, const float* __restrict__ cb)
{
    extern __shared__ uint32_t csm[];
    uint32_t* As = csm;                    // 136*CAP
    uint32_t* Bs = csm + 136 * CAP;        // 64*ZBP

    int tid = threadIdx.x;
    int w = tid >> 5, lane = tid & 31;
    int r4 = lane >> 2, t4 = lane & 3;
    int wm = w >> 1, wn = w & 1;           // warp grid 4(M) x 2(N)
    int n0 = blockIdx.x * 64;
    int by = blockIdx.y;
    int b  = by >> 2;
    int l0 = (by & 3) * 128;

    #pragma unroll
    for (int i = 0; i < 9; i++) {
        int flat = tid + 256 * i;
        if (flat < 132 * 16) {
            int r = flat >> 4, c4 = (flat & 15) * 4;
            int l = l0 - 2 + r;
            float4 v = make_float4(0.f, 0.f, 0.f, 0.f);
            if (l >= 0 && l < SEQL)
                v = *(const float4*)&in[((size_t)b * SEQL + l) * INDIM + c4];
            uint32_t* dst = &As[r * CAP + c4];
            dst[0] = to_tf32(v.x); dst[1] = to_tf32(v.y);
            dst[2] = to_tf32(v.z); dst[3] = to_tf32(v.w);
        }
    }

    float c[2][4][4];
    #pragma unroll
    for (int mt = 0; mt < 2; mt++)
        #pragma unroll
        for (int nt = 0; nt < 4; nt++)
            #pragma unroll
            for (int i = 0; i < 4; i++) c[mt][nt][i] = 0.f;

    for (int tap = 0; tap < 5; tap++) {
        __syncthreads();
        #pragma unroll
        for (int i = 0; i < 4; i++) {
            int flat = tid + 256 * i;
            int k = flat >> 4, c4 = (flat & 15) * 4;
            float4 v = *(const float4*)&ck[((size_t)(tap * 64 + k)) * 256 + n0 + c4];
            uint32_t* dst = &Bs[k * ZBP + c4];
            dst[0] = to_tf32(v.x); dst[1] = to_tf32(v.y);
            dst[2] = to_tf32(v.z); dst[3] = to_tf32(v.w);
        }
        __syncthreads();
        #pragma unroll
        for (int k8 = 0; k8 < 64; k8 += 8) {
            uint32_t a[2][4];
            #pragma unroll
            for (int mt = 0; mt < 2; mt++) {
                int rb = wm * 32 + mt * 16 + tap;
                a[mt][0] = As[(rb + r4) * CAP + k8 + t4];
                a[mt][1] = As[(rb + r4 + 8) * CAP + k8 + t4];
                a[mt][2] = As[(rb + r4) * CAP + k8 + t4 + 4];
                a[mt][3] = As[(rb + r4 + 8) * CAP + k8 + t4 + 4];
            }
            #pragma unroll
            for (int nt = 0; nt < 4; nt++) {
                int coln = wn * 32 + nt * 8 + r4;
                uint32_t b0 = Bs[(k8 + t4) * ZBP + coln];
                uint32_t b1 = Bs[(k8 + t4 + 4) * ZBP + coln];
                mma_tf32(c[0][nt], a[0][0], a[0][1], a[0][2], a[0][3], b0, b1);
                mma_tf32(c[1][nt], a[1][0], a[1][1], a[1][2], a[1][3], b0, b1);
            }
        }
    }

    #pragma unroll
    for (int mt = 0; mt < 2; mt++) {
        #pragma unroll
        for (int nt = 0; nt < 4; nt++) {
            int col = n0 + wn * 32 + nt * 8 + 2 * t4;
            float b0 = __ldg(&cb[col]), b1 = __ldg(&cb[col + 1]);
            int l1 = l0 + wm * 32 + mt * 16 + r4;
            *(float2*)&d_X[((size_t)b * SEQL + l1) * UNITS + col] =
                make_float2(fmaxf(c[mt][nt][0] + b0, 0.f), fmaxf(c[mt][nt][1] + b1, 0.f));
            int l2 = l1 + 8;
            *(float2*)&d_X[((size_t)b * SEQL + l2) * UNITS + col] =
                make_float2(fmaxf(c[mt][nt][2] + b0, 0.f), fmaxf(c[mt][nt][3] + b1, 0.f));
        }
    }
}

// ---------------- ZX = X @ enc_W + enc_b via tf32 MMA (M=131072, N=1024, K=256) ----------------
__global__ __launch_bounds__(256) void gemm_zx_tf32(
    const float* __restrict__ W, const float* __restrict__ bias)
{
    __shared__ uint32_t As[128 * ZAP];
    __shared__ uint32_t Bs[16 * ZBP];
    int tid = threadIdx.x;
    int w = tid >> 5, lane = tid & 31;
    int r4 = lane >> 2, t4 = lane & 3;
    int wm = w >> 1, wn = w & 1;
    int n0 = blockIdx.x * 64;
    int m0 = blockIdx.y * 128;

    float c[2][4][4];
    #pragma unroll
    for (int mt = 0; mt < 2; mt++)
        #pragma unroll
        for (int nt = 0; nt < 4; nt++)
            #pragma unroll
            for (int i = 0; i < 4; i++) c[mt][nt][i] = 0.f;

    for (int k0 = 0; k0 < 256; k0 += 16) {
        #pragma unroll
        for (int i = 0; i < 2; i++) {
            int flat = tid + 256 * i;
            int row = flat >> 2, k4 = (flat & 3) * 4;
            float4 v = *(const float4*)&d_X[(size_t)(m0 + row) * 256 + k0 + k4];
            uint32_t* dst = &As[row * ZAP + k4];
            dst[0] = to_tf32(v.x); dst[1] = to_tf32(v.y);
            dst[2] = to_tf32(v.z); dst[3] = to_tf32(v.w);
        }
        {
            int k = tid >> 4, c4 = (tid & 15) * 4;
            float4 v = *(const float4*)&W[(size_t)(k0 + k) * G4 + n0 + c4];
            uint32_t* dst = &Bs[k * ZBP + c4];
            dst[0] = to_tf32(v.x); dst[1] = to_tf32(v.y);
            dst[2] = to_tf32(v.z); dst[3] = to_tf32(v.w);
        }
        __syncthreads();
        #pragma unroll
        for (int k8 = 0; k8 < 16; k8 += 8) {
            uint32_t a[2][4];
            #pragma unroll
            for (int mt = 0; mt < 2; mt++) {
                int rb = wm * 32 + mt * 16;
                a[mt][0] = As[(rb + r4) * ZAP + k8 + t4];
                a[mt][1] = As[(rb + r4 + 8) * ZAP + k8 + t4];
                a[mt][2] = As[(rb + r4) * ZAP + k8 + t4 + 4];
                a[mt][3] = As[(rb + r4 + 8) * ZAP + k8 + t4 + 4];
            }
            #pragma unroll
            for (int nt = 0; nt < 4; nt++) {
                int coln = wn * 32 + nt * 8 + r4;
                uint32_t b0 = Bs[(k8 + t4) * ZBP + coln];
                uint32_t b1 = Bs[(k8 + t4 + 4) * ZBP + coln];
                mma_tf32(c[0][nt], a[0][0], a[0][1], a[0][2], a[0][3], b0, b1);
                mma_tf32(c[1][nt], a[1][0], a[1][1], a[1][2], a[1][3], b0, b1);
            }
        }
        __syncthreads();
    }
    #pragma unroll
    for (int mt = 0; mt < 2; mt++) {
        #pragma unroll
        for (int nt = 0; nt < 4; nt++) {
            int col = n0 + wn * 32 + nt * 8 + 2 * t4;
            float b0 = __ldg(&bias[col]), b1 = __ldg(&bias[col + 1]);
            int m_r = m0 + wm * 32 + mt * 16 + r4;
            int bi = m_r >> 9, tt = m_r & 511;
            *(float2*)&d_ZX[((size_t)tt * BATCH + bi) * G4 + col] =
                make_float2(c[mt][nt][0] + b0, c[mt][nt][1] + b1);
            int m_r2 = m_r + 8;
            int bi2 = m_r2 >> 9, tt2 = m_r2 & 511;
            *(float2*)&d_ZX[((size_t)tt2 * BATCH + bi2) * G4 + col] =
                make_float2(c[mt][nt][2] + b0, c[mt][nt][3] + b1);
        }
    }
}

// no-op pad so lstm_persistent stays at launch index 3 (ncu capture slot)
__global__ void pad_kernel() {}

// ---------------- persistent LSTM: two interleaved batch-group streams per CTA ----------------
// 128 CTAs x 256 threads. 16 groups of 16 batches; CTA (ct,bt) handles groups
// gA=bt and gB=bt+8 for units [ct*16, ct*16+16). Per group sub-step:
// wait(split barrier) -> stage h (16x256) -> m16 MMA (split-k4) -> reduce -> gates -> arrive.
// Each group's barrier round-trip is hidden under the OTHER group's sub-step.
// Barrier = R10-proven atomic counter + monotonic gen per group (padded lines).
__global__ __launch_bounds__(256, 1) void lstm_persistent(
    const float* __restrict__ encU, const float* __restrict__ cellW,
    const float* __restrict__ cellU, const float* __restrict__ cellB)
{
    __shared__ __align__(16) float hT[16 * HP];       // 16896 B
    __shared__ __align__(16) float red[4 * 16 * RP];  // 18432 B

    int tid  = threadIdx.x;
    int w    = tid >> 5;
    int lane = tid & 31;
    int r4 = lane >> 2;
    int t4 = lane & 3;
    int kh = w >> 1;             // 0..3  k-quarter
    int ch = w & 1;              // 0..1  col-half
    int ct = blockIdx.x & 15;
    int bt = blockIdx.x >> 4;    // 0..7 -> groups bt, bt+8
    int u0 = ct * 16;

    int guu = tid & 15;
    int gbl = tid >> 4;          // 0..15 (one batch per group)
    int gu  = u0 + guu;

    int bcol[4];
    #pragma unroll
    for (int nt = 0; nt < 4; nt++) {
        int col = ch * 32 + nt * 8 + r4;
        bcol[nt] = (col >> 4) * 256 + u0 + (col & 15);
    }

    // ---- encoder U -> B fragments (tf32), once; shared by both groups ----
    uint32_t Bf[8][4][2];
    #pragma unroll
    for (int kk = 0; kk < 8; kk++) {
        int k = kh * 64 + kk * 8 + t4;
        #pragma unroll
        for (int nt = 0; nt < 4; nt++) {
            Bf[kk][nt][0] = to_tf32(__ldg(&encU[(size_t)k * G4 + bcol[nt]]));
            Bf[kk][nt][1] = to_tf32(__ldg(&encU[(size_t)(k + 4) * G4 + bcol[nt]]));
        }
    }

    float cst[2] = {0.f, 0.f};          // c state, one batch per group
    float bz[4]  = {0.f, 0.f, 0.f, 0.f};
    unsigned seen[2] = {0u, 0u};        // barrier gen snapshots (tid0 only meaningful)

    // ---- prefetch zini for t=0, both groups ----
    float zini[2][4];
    #pragma unroll
    for (int gi = 0; gi < 2; gi++) {
        int b = (bt + gi * 8) * 16 + gbl;
        const float* r = d_ZX + (size_t)b * G4 + gu;
        #pragma unroll
        for (int g = 0; g < 4; g++) zini[gi][g] = __ldcg(r + g * 256);
    }

    #pragma unroll 1
    for (int s = 0; s < SEQL + OUTSTEPS; s++) {
        int dec = (s >= SEQL);
        int t = dec ? s - SEQL : s;

        if (s == SEQL) {   // decoder weights: cell_W + cell_U folded (shared by both groups)
            #pragma unroll
            for (int kk = 0; kk < 8; kk++) {
                int k = kh * 64 + kk * 8 + t4;
                #pragma unroll
                for (int nt = 0; nt < 4; nt++) {
                    size_t o0 = (size_t)k * G4 + bcol[nt];
                    size_t o1 = (size_t)(k + 4) * G4 + bcol[nt];
                    Bf[kk][nt][0] = to_tf32(__ldg(&cellW[o0]) + __ldg(&cellU[o0]));
                    Bf[kk][nt][1] = to_tf32(__ldg(&cellW[o1]) + __ldg(&cellU[o1]));
                }
            }
            #pragma unroll
            for (int g = 0; g < 4; g++) bz[g] = __ldg(cellB + g * 256 + gu);
        }

        #pragma unroll
        for (int gi = 0; gi < 2; gi++) {
            int grp = bt + gi * 8;
            int bb0 = grp * 16;

            // ---- wait: group's previous round complete (hidden under other group's work) ----
            if (s > 0) {
                if (tid == 0) {
                    volatile unsigned* gp = &g_gen2[grp][0];
                    while (*gp == seen[gi]) { }
                    __threadfence();
                }
            }
            __syncthreads();

            // ---- stage h_prev (tf32 bits) into hT[bl][k] ----
            if (s == 0) {
                for (int idx = tid; idx < 16 * HP; idx += 256) hT[idx] = 0.f;
            } else {
                const float* hin = d_HX[s & 1];
                #pragma unroll
                for (int i = 0; i < 4; i++) {
                    int flat = tid + 256 * i;
                    int bl = flat >> 6;
                    int k4 = (flat & 63) * 4;
                    float4 v = __ldcg((const float4*)(hin + (size_t)(bb0 + bl) * UNITS + k4));
                    *(float4*)&hT[bl * HP + k4] = v;
                }
            }
            __syncthreads();

            // ---- z partial = h @ U over this warp's k-quarter (m=16) ----
            float c0[4][4];
            #pragma unroll
            for (int nt = 0; nt < 4; nt++)
                #pragma unroll
                for (int i = 0; i < 4; i++) c0[nt][i] = 0.f;

            #pragma unroll
            for (int kk = 0; kk < 8; kk++) {
                int k0 = kh * 64 + kk * 8 + t4;
                uint32_t a0 = __float_as_uint(hT[r4 * HP + k0]);
                uint32_t a1 = __float_as_uint(hT[(r4 + 8) * HP + k0]);
                uint32_t a2 = __float_as_uint(hT[r4 * HP + k0 + 4]);
                uint32_t a3 = __float_as_uint(hT[(r4 + 8) * HP + k0 + 4]);
                #pragma unroll
                for (int nt = 0; nt < 4; nt++)
                    mma_tf32(c0[nt], a0, a1, a2, a3, Bf[kk][nt][0], Bf[kk][nt][1]);
            }

            // ---- scatter partials to red[kh][row][col] ----
            #pragma unroll
            for (int nt = 0; nt < 4; nt++) {
                int cb = ch * 32 + nt * 8 + 2 * t4;
                float* r0 = &red[(kh * 16 + r4) * RP + cb];
                r0[0] = c0[nt][0];
                r0[1] = c0[nt][1];
                float* r1 = &red[(kh * 16 + r4 + 8) * RP + cb];
                r1[0] = c0[nt][2];
                r1[1] = c0[nt][3];
            }
            __syncthreads();

            // ---- gates (thread = (guu, gbl)), one batch ----
            {
                float z[4];
                #pragma unroll
                for (int g = 0; g < 4; g++) {
                    float acc = dec ? bz[g] : zini[gi][g];
                    #pragma unroll
                    for (int q = 0; q < 4; q++)
                        acc += red[(q * 16 + gbl) * RP + g * 16 + guu];
                    z[g] = acc;
                }

                float ig = fast_sigmoid(z[0]);
                float fg = fast_sigmoid(z[1]);
                float gg = fast_tanh(z[2]);
                float og = fast_sigmoid(z[3]);
                float cn = fg * cst[gi] + ig * gg;
                float hn = og * fast_tanh(cn);
                cst[gi] = cn;

                int b = bb0 + gbl;
                if (!dec) d_HSEQ[((size_t)b * SEQL + t) * UNITS + gu] = hn;
                else      d_FSEQ[((size_t)b * OUTSTEPS + t) * UNITS + gu] = hn;
                d_HX[(s + 1) & 1][(size_t)b * UNITS + gu] = __uint_as_float(to_tf32(hn));
            }

            // ---- prefetch next encoder step's zini (hidden under barrier) ----
            if (s + 1 < SEQL) {
                const float* r = d_ZX + ((size_t)(s + 1) * BATCH + bb0 + gbl) * G4 + gu;
                #pragma unroll
                for (int g = 0; g < 4; g++) zini[gi][g] = __ldcg(r + g * 256);
            }
            __syncthreads();

            // ---- arrive (non-blocking): release this CTA's h stores for round s ----
            if (tid == 0) {
                seen[gi] = *(volatile unsigned*)&g_gen2[grp][0];
                __threadfence();
                if (atomicAdd(&g_cnt2[grp][0], 1u) == 15) {
                    *(volatile unsigned*)&g_cnt2[grp][0] = 0;
                    __threadfence();
                    atomicAdd(&g_gen2[grp][0], 1u);
                }
            }
        }
    }
}

// ---------------- backcast = HSEQ @ back_W + back_b (M=131072, N=64, K=256), f32x2 ----------------
__global__ __launch_bounds__(256) void gemm_back_kernel(
    const float* __restrict__ Bw, const float* __restrict__ bias, float* __restrict__ out)
{
    __shared__ __align__(16) ull   As2[16 * 64];
    __shared__ __align__(16) float Bs [16 * 64];
    int tid = threadIdx.x;
    int m0 = blockIdx.x * 64;
    int tx = tid & 15, ty = tid >> 4;
    ull acc[4][2];
    #pragma unroll
    for (int i = 0; i < 4; i++) { acc[i][0] = 0ull; acc[i][1] = 0ull; }
    int lam = tid >> 2, lak = (tid & 3) * 4;
    int lbk = tid >> 4, lbn = (tid & 15) * 4;
    for (int k0 = 0; k0 < 256; k0 += 16) {
        float4 av = *(const float4*)&d_HSEQ[(size_t)(m0 + lam) * 256 + k0 + lak];
        float4 bv = *(const float4*)&Bw[(size_t)(k0 + lbk) * 64 + lbn];
        As2[(lak + 0) * 64 + lam] = pk2(av.x, av.x);
        As2[(lak + 1) * 64 + lam] = pk2(av.y, av.y);
        As2[(lak + 2) * 64 + lam] = pk2(av.z, av.z);
        As2[(lak + 3) * 64 + lam] = pk2(av.w, av.w);
        *(float4*)&Bs[lbk * 64 + lbn] = bv;
        __syncthreads();
        #pragma unroll
        for (int k = 0; k < 16; k++) {
            ulonglong2 a01 = *(const ulonglong2*)&As2[k * 64 + ty * 4];
            ulonglong2 a23 = *(const ulonglong2*)&As2[k * 64 + ty * 4 + 2];
            ulonglong2 bq  = *(const ulonglong2*)&Bs[k * 64 + tx * 4];
            ffma2(acc[0][0], a01.x, bq.x); ffma2(acc[0][1], a01.x, bq.y);
            ffma2(acc[1][0], a01.y, bq.x); ffma2(acc[1][1], a01.y, bq.y);
            ffma2(acc[2][0], a23.x, bq.x); ffma2(acc[2][1], a23.x, bq.y);
            ffma2(acc[3][0], a23.y, bq.x); ffma2(acc[3][1], a23.y, bq.y);
        }
        __syncthreads();
    }
    #pragma unroll
    for (int i = 0; i < 4; i++) {
        int m = m0 + ty * 4 + i;
        #pragma unroll
        for (int j = 0; j < 2; j++) {
            float lo, hi; upk2(acc[i][j], lo, hi);
            int n = tx * 4 + j * 2;
            out[(size_t)m * 64 + n]     = lo + bias[n];
            out[(size_t)m * 64 + n + 1] = hi + bias[n + 1];
        }
    }
}

// ---------------- forecast = FSEQ @ fore_W + fore_b ----------------
__global__ __launch_bounds__(256) void forecast_kernel(
    const float* __restrict__ Wf, const float* __restrict__ bf, float* __restrict__ out)
{
    __shared__ __align__(16) float rows[8][256];
    int tid = threadIdx.x;
    int m0 = blockIdx.x * 8;
    #pragma unroll
    for (int i = 0; i < 8; i++) {
        int flat = tid + 256 * i;
        int r = flat >> 8, cc = flat & 255;
        rows[r][cc] = d_FSEQ[(size_t)(m0 + r) * 256 + cc];
    }
    __syncthreads();
    int r = tid >> 5, n = tid & 31;
    float acc = bf[n];
    #pragma unroll 8
    for (int k = 0; k < 256; k++) acc += rows[r][k] * Wf[k * 32 + n];
    out[(size_t)(m0 + r) * 32 + n] = acc;
}

// ---------------- launch ----------------
extern "C" void kernel_launch(void* const* d_in, const int* in_sizes, int n_in,
                              void* d_out, int out_size)
{
    const float* inputs = (const float*)d_in[0];
    const float* conv_k = (const float*)d_in[1];
    const float* conv_b = (const float*)d_in[2];
    const float* enc_W  = (const float*)d_in[3];
    const float* enc_U  = (const float*)d_in[4];
    const float* enc_b  = (const float*)d_in[5];
    const float* cell_W = (const float*)d_in[6];
    const float* cell_U = (const float*)d_in[7];
    const float* cell_b = (const float*)d_in[8];
    const float* fore_W = (const float*)d_in[9];
    const float* fore_b = (const float*)d_in[10];
    const float* back_W = (const float*)d_in[11];
    const float* back_b = (const float*)d_in[12];
    float* out = (float*)d_out;

    const int conv_smem = (136 * CAP + 64 * ZBP) * 4;      // 55424 B
    cudaFuncSetAttribute(conv_tf32,
                         cudaFuncAttributeMaxDynamicSharedMemorySize, conv_smem);

    conv_tf32<<<dim3(4, BATCH * 4), 256, conv_smem>>>(inputs, conv_k, conv_b);     // idx 0
    gemm_zx_tf32<<<dim3(G4 / 64, (BATCH * SEQL) / 128), 256>>>(enc_W, enc_b);      // idx 1
    pad_kernel<<<1, 32>>>();                                                       // idx 2
    lstm_persistent<<<NCTA_REC, 256>>>(enc_U, cell_W, cell_U, cell_b);             // idx 3 (ncu slot)
    forecast_kernel<<<(BATCH * OUTSTEPS) / 8, 256>>>(fore_W, fore_b, out);
    gemm_back_kernel<<<(BATCH * SEQL) / 64, 256>>>(back_W, back_b,
                                                   out + (size_t)BATCH * OUTSTEPS * OUTDIMS);
}

// round 15
// speedup vs baseline: 1.9213x; 1.9213x over previous
#include <cuda_runtime.h>
#include <cstdint>
#include <math.h>

#define BATCH    256
#define SEQL     512
#define INDIM    64
#define UNITS    256
#define OUTSTEPS 64
#define OUTDIMS  32
#define G4       1024   // 4 * UNITS
#define NCTA_REC 128
#define HP       264    // hT row pitch (floats)
#define RP       72     // red row pitch
#define ZAP      20     // ZX gemm A smem pitch
#define ZBP      72     // B smem pitch (ZX + conv)
#define CAP      68     // conv A smem pitch

typedef unsigned long long ull;

// ---------------- scratch (static device globals; no allocation) ----------------
__device__ float d_X[BATCH * SEQL * UNITS];            // conv output
__device__ float d_ZX[(size_t)SEQL * BATCH * G4];      // x@W + b, [t][b][1024]
__device__ float d_HSEQ[BATCH * SEQL * UNITS];         // encoder hidden seq
__device__ float d_FSEQ[BATCH * OUTSTEPS * UNITS];     // decoder hidden seq
__device__ float d_HX[2][BATCH * UNITS];               // ping-pong h, tf32 bits
__device__ unsigned g_cnt2[8][32];                      // per-batch-group barrier (padded lines)
__device__ unsigned g_gen2[8][32];

// ---------------- f32x2 helpers (backcast) ----------------
__device__ __forceinline__ ull pk2(float lo, float hi) {
    ull r; asm("mov.b64 %0, {%1, %2};" : "=l"(r) : "f"(lo), "f"(hi)); return r;
}
__device__ __forceinline__ void upk2(ull v, float& lo, float& hi) {
    asm("mov.b64 {%0, %1}, %2;" : "=f"(lo), "=f"(hi) : "l"(v));
}
__device__ __forceinline__ void ffma2(ull& d, ull a, ull b) {
    asm("fma.rn.f32x2 %0, %1, %2, %0;" : "+l"(d) : "l"(a), "l"(b));
}

// tf32 + mma helpers
__device__ __forceinline__ uint32_t to_tf32(float x) {
    uint32_t r; asm("cvt.rna.tf32.f32 %0, %1;" : "=r"(r) : "f"(x)); return r;
}
__device__ __forceinline__ void mma_tf32(float* c,
    uint32_t a0, uint32_t a1, uint32_t a2, uint32_t a3, uint32_t b0, uint32_t b1)
{
    asm("mma.sync.aligned.m16n8k8.row.col.f32.tf32.tf32.f32 "
        "{%0,%1,%2,%3}, {%4,%5,%6,%7}, {%8,%9}, {%0,%1,%2,%3};"
        : "+f"(c[0]), "+f"(c[1]), "+f"(c[2]), "+f"(c[3])
        : "r"(a0), "r"(a1), "r"(a2), "r"(a3), "r"(b0), "r"(b1));
}

// fast, overflow-safe gate functions
__device__ __forceinline__ float fast_sigmoid(float x) {
    return __fdividef(1.f, 1.f + __expf(-x));
}
__device__ __forceinline__ float fast_tanh(float x) {
    float e = __expf(-2.f * fabsf(x));
    float t = __fdividef(1.f - e, 1.f + e);
    return copysignf(t, x);
}

// ---------------- conv1d 'same' (K=5) + bias + relu via tf32 MMA ----------------
__global__ __launch_bounds__(256) void conv_tf32(
    const float* __restrict__ in, const float* __restrict__ ck, const float* __restrict__ cb)
{
    extern __shared__ uint32_t csm[];
    uint32_t* As = csm;                    // 136*CAP
    uint32_t* Bs = csm + 136 * CAP;        // 64*ZBP

    int tid = threadIdx.x;
    int w = tid >> 5, lane = tid & 31;
    int r4 = lane >> 2, t4 = lane & 3;
    int wm = w >> 1, wn = w & 1;           // warp grid 4(M) x 2(N)
    int n0 = blockIdx.x * 64;
    int by = blockIdx.y;
    int b  = by >> 2;
    int l0 = (by & 3) * 128;

    #pragma unroll
    for (int i = 0; i < 9; i++) {
        int flat = tid + 256 * i;
        if (flat < 132 * 16) {
            int r = flat >> 4, c4 = (flat & 15) * 4;
            int l = l0 - 2 + r;
            float4 v = make_float4(0.f, 0.f, 0.f, 0.f);
            if (l >= 0 && l < SEQL)
                v = *(const float4*)&in[((size_t)b * SEQL + l) * INDIM + c4];
            uint32_t* dst = &As[r * CAP + c4];
            dst[0] = to_tf32(v.x); dst[1] = to_tf32(v.y);
            dst[2] = to_tf32(v.z); dst[3] = to_tf32(v.w);
        }
    }

    float c[2][4][4];
    #pragma unroll
    for (int mt = 0; mt < 2; mt++)
        #pragma unroll
        for (int nt = 0; nt < 4; nt++)
            #pragma unroll
            for (int i = 0; i < 4; i++) c[mt][nt][i] = 0.f;

    for (int tap = 0; tap < 5; tap++) {
        __syncthreads();
        #pragma unroll
        for (int i = 0; i < 4; i++) {
            int flat = tid + 256 * i;
            int k = flat >> 4, c4 = (flat & 15) * 4;
            float4 v = *(const float4*)&ck[((size_t)(tap * 64 + k)) * 256 + n0 + c4];
            uint32_t* dst = &Bs[k * ZBP + c4];
            dst[0] = to_tf32(v.x); dst[1] = to_tf32(v.y);
            dst[2] = to_tf32(v.z); dst[3] = to_tf32(v.w);
        }
        __syncthreads();
        #pragma unroll
        for (int k8 = 0; k8 < 64; k8 += 8) {
            uint32_t a[2][4];
            #pragma unroll
            for (int mt = 0; mt < 2; mt++) {
                int rb = wm * 32 + mt * 16 + tap;
                a[mt][0] = As[(rb + r4) * CAP + k8 + t4];
                a[mt][1] = As[(rb + r4 + 8) * CAP + k8 + t4];
                a[mt][2] = As[(rb + r4) * CAP + k8 + t4 + 4];
                a[mt][3] = As[(rb + r4 + 8) * CAP + k8 + t4 + 4];
            }
            #pragma unroll
            for (int nt = 0; nt < 4; nt++) {
                int coln = wn * 32 + nt * 8 + r4;
                uint32_t b0 = Bs[(k8 + t4) * ZBP + coln];
                uint32_t b1 = Bs[(k8 + t4 + 4) * ZBP + coln];
                mma_tf32(c[0][nt], a[0][0], a[0][1], a[0][2], a[0][3], b0, b1);
                mma_tf32(c[1][nt], a[1][0], a[1][1], a[1][2], a[1][3], b0, b1);
            }
        }
    }

    #pragma unroll
    for (int mt = 0; mt < 2; mt++) {
        #pragma unroll
        for (int nt = 0; nt < 4; nt++) {
            int col = n0 + wn * 32 + nt * 8 + 2 * t4;
            float b0 = __ldg(&cb[col]), b1 = __ldg(&cb[col + 1]);
            int l1 = l0 + wm * 32 + mt * 16 + r4;
            *(float2*)&d_X[((size_t)b * SEQL + l1) * UNITS + col] =
                make_float2(fmaxf(c[mt][nt][0] + b0, 0.f), fmaxf(c[mt][nt][1] + b1, 0.f));
            int l2 = l1 + 8;
            *(float2*)&d_X[((size_t)b * SEQL + l2) * UNITS + col] =
                make_float2(fmaxf(c[mt][nt][2] + b0, 0.f), fmaxf(c[mt][nt][3] + b1, 0.f));
        }
    }
}

// ---------------- ZX = X @ enc_W + enc_b via tf32 MMA, register double-buffer ----------------
__global__ __launch_bounds__(256) void gemm_zx_tf32(
    const float* __restrict__ W, const float* __restrict__ bias)
{
    __shared__ uint32_t As[128 * ZAP];
    __shared__ uint32_t Bs[16 * ZBP];
    int tid = threadIdx.x;
    int w = tid >> 5, lane = tid & 31;
    int r4 = lane >> 2, t4 = lane & 3;
    int wm = w >> 1, wn = w & 1;
    int n0 = blockIdx.x * 64;
    int m0 = blockIdx.y * 128;

    // A staging indices: 2 float4 per thread; B: 1 float4 per thread
    int arow0 = tid >> 2,          ak0 = (tid & 3) * 4;
    int arow1 = (tid + 256) >> 2,  ak1 = ((tid + 256) & 3) * 4;
    int bk = tid >> 4, bc4 = (tid & 15) * 4;

    float c[2][4][4];
    #pragma unroll
    for (int mt = 0; mt < 2; mt++)
        #pragma unroll
        for (int nt = 0; nt < 4; nt++)
            #pragma unroll
            for (int i = 0; i < 4; i++) c[mt][nt][i] = 0.f;

    // prologue: load k0=0 tiles into registers
    float4 avr0 = *(const float4*)&d_X[(size_t)(m0 + arow0) * 256 + ak0];
    float4 avr1 = *(const float4*)&d_X[(size_t)(m0 + arow1) * 256 + ak1];
    float4 bvr  = *(const float4*)&W[(size_t)bk * G4 + n0 + bc4];

    for (int k0 = 0; k0 < 256; k0 += 16) {
        // store current regs to smem (cvt to tf32)
        {
            uint32_t* d0 = &As[arow0 * ZAP + ak0];
            d0[0] = to_tf32(avr0.x); d0[1] = to_tf32(avr0.y);
            d0[2] = to_tf32(avr0.z); d0[3] = to_tf32(avr0.w);
            uint32_t* d1 = &As[arow1 * ZAP + ak1];
            d1[0] = to_tf32(avr1.x); d1[1] = to_tf32(avr1.y);
            d1[2] = to_tf32(avr1.z); d1[3] = to_tf32(avr1.w);
            uint32_t* db = &Bs[bk * ZBP + bc4];
            db[0] = to_tf32(bvr.x); db[1] = to_tf32(bvr.y);
            db[2] = to_tf32(bvr.z); db[3] = to_tf32(bvr.w);
        }
        __syncthreads();

        // prefetch next k-chunk into registers (LDG latency hidden under MMA)
        if (k0 + 16 < 256) {
            int kn = k0 + 16;
            avr0 = *(const float4*)&d_X[(size_t)(m0 + arow0) * 256 + kn + ak0];
            avr1 = *(const float4*)&d_X[(size_t)(m0 + arow1) * 256 + kn + ak1];
            bvr  = *(const float4*)&W[(size_t)(kn + bk) * G4 + n0 + bc4];
        }

        #pragma unroll
        for (int k8 = 0; k8 < 16; k8 += 8) {
            uint32_t a[2][4];
            #pragma unroll
            for (int mt = 0; mt < 2; mt++) {
                int rb = wm * 32 + mt * 16;
                a[mt][0] = As[(rb + r4) * ZAP + k8 + t4];
                a[mt][1] = As[(rb + r4 + 8) * ZAP + k8 + t4];
                a[mt][2] = As[(rb + r4) * ZAP + k8 + t4 + 4];
                a[mt][3] = As[(rb + r4 + 8) * ZAP + k8 + t4 + 4];
            }
            #pragma unroll
            for (int nt = 0; nt < 4; nt++) {
                int coln = wn * 32 + nt * 8 + r4;
                uint32_t b0 = Bs[(k8 + t4) * ZBP + coln];
                uint32_t b1 = Bs[(k8 + t4 + 4) * ZBP + coln];
                mma_tf32(c[0][nt], a[0][0], a[0][1], a[0][2], a[0][3], b0, b1);
                mma_tf32(c[1][nt], a[1][0], a[1][1], a[1][2], a[1][3], b0, b1);
            }
        }
        __syncthreads();
    }
    #pragma unroll
    for (int mt = 0; mt < 2; mt++) {
        #pragma unroll
        for (int nt = 0; nt < 4; nt++) {
            int col = n0 + wn * 32 + nt * 8 + 2 * t4;
            float b0 = __ldg(&bias[col]), b1 = __ldg(&bias[col + 1]);
            int m_r = m0 + wm * 32 + mt * 16 + r4;
            int bi = m_r >> 9, tt = m_r & 511;
            *(float2*)&d_ZX[((size_t)tt * BATCH + bi) * G4 + col] =
                make_float2(c[mt][nt][0] + b0, c[mt][nt][1] + b1);
            int m_r2 = m_r + 8;
            int bi2 = m_r2 >> 9, tt2 = m_r2 & 511;
            *(float2*)&d_ZX[((size_t)tt2 * BATCH + bi2) * G4 + col] =
                make_float2(c[mt][nt][2] + b0, c[mt][nt][3] + b1);
        }
    }
}

// no-op pad so lstm_persistent stays at launch index 3 (ncu capture slot)
__global__ void pad_kernel() {}

// ---------------- per-batch-group barrier: 16 CTAs, own padded line (R10/R12-proven) ----------------
__device__ __forceinline__ void group_sync(int bt) {
    __syncthreads();
    if (threadIdx.x == 0) {
        unsigned gen = *(volatile unsigned*)&g_gen2[bt][0];
        __threadfence();
        if (atomicAdd(&g_cnt2[bt][0], 1u) == 15) {
            *(volatile unsigned*)&g_cnt2[bt][0] = 0;
            __threadfence();
            atomicAdd(&g_gen2[bt][0], 1u);
        } else {
            while (*(volatile unsigned*)&g_gen2[bt][0] == gen) { }
        }
        __threadfence();
    }
    __syncthreads();
}

// ---------------- persistent LSTM: tf32 warp-MMA, split-k4 (R12-proven config) ----------------
__global__ __launch_bounds__(256, 1) void lstm_persistent(
    const float* __restrict__ encU, const float* __restrict__ cellW,
    const float* __restrict__ cellU, const float* __restrict__ cellB)
{
    extern __shared__ float smem_f[];
    float* hT  = smem_f;                 // 32*HP floats
    float* red = smem_f + 32 * HP;       // 4*32*RP floats

    int tid  = threadIdx.x;
    int w    = tid >> 5;
    int lane = tid & 31;
    int r4 = lane >> 2;
    int t4 = lane & 3;
    int kh = w >> 1;             // 0..3  k-quarter
    int ch = w & 1;              // 0..1  col-half
    int ct = blockIdx.x & 15;
    int bt = blockIdx.x >> 4;
    int u0 = ct * 16;
    int b0 = bt * 32;

    int guu = tid & 15;
    int gbl = tid >> 4;
    int gu  = u0 + guu;

    int bcol[4];
    #pragma unroll
    for (int nt = 0; nt < 4; nt++) {
        int col = ch * 32 + nt * 8 + r4;
        bcol[nt] = (col >> 4) * 256 + u0 + (col & 15);
    }

    // ---- encoder U -> B fragments (tf32), once ----
    uint32_t Bf[8][4][2];
    #pragma unroll
    for (int kk = 0; kk < 8; kk++) {
        int k = kh * 64 + kk * 8 + t4;
        #pragma unroll
        for (int nt = 0; nt < 4; nt++) {
            Bf[kk][nt][0] = to_tf32(__ldg(&encU[(size_t)k * G4 + bcol[nt]]));
            Bf[kk][nt][1] = to_tf32(__ldg(&encU[(size_t)(k + 4) * G4 + bcol[nt]]));
        }
    }

    float cst[2] = {0.f, 0.f};
    float bz[4]  = {0.f, 0.f, 0.f, 0.f};

    // ---- prefetch zini for t=0 ----
    float zini[2][4];
    #pragma unroll
    for (int p = 0; p < 2; p++) {
        const float* r = d_ZX + ((size_t)(b0 + p * 16 + gbl)) * G4 + gu;
        #pragma unroll
        for (int g = 0; g < 4; g++) zini[p][g] = __ldcg(r + g * 256);
    }

    #pragma unroll 1
    for (int s = 0; s < SEQL + OUTSTEPS; s++) {
        int dec = (s >= SEQL);
        int t = dec ? s - SEQL : s;

        if (s == SEQL) {   // decoder weights: cell_W + cell_U folded
            #pragma unroll
            for (int kk = 0; kk < 8; kk++) {
                int k = kh * 64 + kk * 8 + t4;
                #pragma unroll
                for (int nt = 0; nt < 4; nt++) {
                    size_t o0 = (size_t)k * G4 + bcol[nt];
                    size_t o1 = (size_t)(k + 4) * G4 + bcol[nt];
                    Bf[kk][nt][0] = to_tf32(__ldg(&cellW[o0]) + __ldg(&cellU[o0]));
                    Bf[kk][nt][1] = to_tf32(__ldg(&cellW[o1]) + __ldg(&cellU[o1]));
                }
            }
            #pragma unroll
            for (int g = 0; g < 4; g++) bz[g] = __ldg(cellB + g * 256 + gu);
        }

        // ---- stage h_prev (tf32 bits) from d_HX into hT[b][k] ----
        if (s == 0) {
            for (int idx = tid; idx < 32 * HP; idx += 256) hT[idx] = 0.f;
        } else {
            const float* hin = d_HX[s & 1];
            #pragma unroll
            for (int i = 0; i < 8; i++) {
                int flat = tid + 256 * i;
                int bl = flat >> 6;
                int k4 = (flat & 63) * 4;
                float4 v = __ldcg((const float4*)(hin + (size_t)(b0 + bl) * UNITS + k4));
                *(float4*)&hT[bl * HP + k4] = v;
            }
        }
        __syncthreads();

        // ---- z partial = h @ U over this warp's k-quarter ----
        float c0[2][4][4];
        #pragma unroll
        for (int mt = 0; mt < 2; mt++)
            #pragma unroll
            for (int nt = 0; nt < 4; nt++)
                #pragma unroll
                for (int i = 0; i < 4; i++) c0[mt][nt][i] = 0.f;

        #pragma unroll
        for (int kk = 0; kk < 8; kk++) {
            int k0 = kh * 64 + kk * 8 + t4;
            uint32_t a[2][4];
            #pragma unroll
            for (int mt = 0; mt < 2; mt++) {
                int rb = mt * 16;
                a[mt][0] = __float_as_uint(hT[(rb + r4) * HP + k0]);
                a[mt][1] = __float_as_uint(hT[(rb + r4 + 8) * HP + k0]);
                a[mt][2] = __float_as_uint(hT[(rb + r4) * HP + k0 + 4]);
                a[mt][3] = __float_as_uint(hT[(rb + r4 + 8) * HP + k0 + 4]);
            }
            #pragma unroll
            for (int nt = 0; nt < 4; nt++) {
                mma_tf32(c0[0][nt], a[0][0], a[0][1], a[0][2], a[0][3],
                         Bf[kk][nt][0], Bf[kk][nt][1]);
                mma_tf32(c0[1][nt], a[1][0], a[1][1], a[1][2], a[1][3],
                         Bf[kk][nt][0], Bf[kk][nt][1]);
            }
        }

        // ---- scatter partials to red[kh][row][col] ----
        #pragma unroll
        for (int mt = 0; mt < 2; mt++) {
            #pragma unroll
            for (int nt = 0; nt < 4; nt++) {
                int cb = ch * 32 + nt * 8 + 2 * t4;
                float* r0 = &red[((kh * 32) + mt * 16 + r4) * RP + cb];
                r0[0] = c0[mt][nt][0];
                r0[1] = c0[mt][nt][1];
                float* r1 = &red[((kh * 32) + mt * 16 + r4 + 8) * RP + cb];
                r1[0] = c0[mt][nt][2];
                r1[1] = c0[mt][nt][3];
            }
        }
        __syncthreads();

        // ---- gates (thread = (guu, gbl)), batches gbl and gbl+16 ----
        float* hx = d_HX[(s + 1) & 1];
        #pragma unroll
        for (int p = 0; p < 2; p++) {
            int bl = p * 16 + gbl;
            float z[4];
            #pragma unroll
            for (int g = 0; g < 4; g++) {
                float acc = dec ? bz[g] : zini[p][g];
                #pragma unroll
                for (int q = 0; q < 4; q++)
                    acc += red[(q * 32 + bl) * RP + g * 16 + guu];
                z[g] = acc;
            }

            float ig = fast_sigmoid(z[0]);
            float fg = fast_sigmoid(z[1]);
            float gg = fast_tanh(z[2]);
            float og = fast_sigmoid(z[3]);
            float cn = fg * cst[p] + ig * gg;
            float hn = og * fast_tanh(cn);
            cst[p] = cn;

            int b = b0 + bl;
            if (!dec) d_HSEQ[((size_t)b * SEQL + t) * UNITS + gu] = hn;
            else      d_FSEQ[((size_t)b * OUTSTEPS + t) * UNITS + gu] = hn;
            hx[(size_t)b * UNITS + gu] = __uint_as_float(to_tf32(hn));
        }

        // ---- prefetch next encoder step's zini (hidden under barrier) ----
        if (s + 1 < SEQL) {
            int tn = s + 1;
            #pragma unroll
            for (int p = 0; p < 2; p++) {
                const float* r = d_ZX + ((size_t)tn * BATCH + b0 + p * 16 + gbl) * G4 + gu;
                #pragma unroll
                for (int g = 0; g < 4; g++) zini[p][g] = __ldcg(r + g * 256);
            }
        }

        group_sync(bt);
    }
}

// ---------------- backcast = HSEQ @ back_W + back_b (M=131072, N=64, K=256), f32x2 ----------------
__global__ __launch_bounds__(256) void gemm_back_kernel(
    const float* __restrict__ Bw, const float* __restrict__ bias, float* __restrict__ out)
{
    __shared__ __align__(16) ull   As2[16 * 64];
    __shared__ __align__(16) float Bs [16 * 64];
    int tid = threadIdx.x;
    int m0 = blockIdx.x * 64;
    int tx = tid & 15, ty = tid >> 4;
    ull acc[4][2];
    #pragma unroll
    for (int i = 0; i < 4; i++) { acc[i][0] = 0ull; acc[i][1] = 0ull; }
    int lam = tid >> 2, lak = (tid & 3) * 4;
    int lbk = tid >> 4, lbn = (tid & 15) * 4;
    for (int k0 = 0; k0 < 256; k0 += 16) {
        float4 av = *(const float4*)&d_HSEQ[(size_t)(m0 + lam) * 256 + k0 + lak];
        float4 bv = *(const float4*)&Bw[(size_t)(k0 + lbk) * 64 + lbn];
        As2[(lak + 0) * 64 + lam] = pk2(av.x, av.x);
        As2[(lak + 1) * 64 + lam] = pk2(av.y, av.y);
        As2[(lak + 2) * 64 + lam] = pk2(av.z, av.z);
        As2[(lak + 3) * 64 + lam] = pk2(av.w, av.w);
        *(float4*)&Bs[lbk * 64 + lbn] = bv;
        __syncthreads();
        #pragma unroll
        for (int k = 0; k < 16; k++) {
            ulonglong2 a01 = *(const ulonglong2*)&As2[k * 64 + ty * 4];
            ulonglong2 a23 = *(const ulonglong2*)&As2[k * 64 + ty * 4 + 2];
            ulonglong2 bq  = *(const ulonglong2*)&Bs[k * 64 + tx * 4];
            ffma2(acc[0][0], a01.x, bq.x); ffma2(acc[0][1], a01.x, bq.y);
            ffma2(acc[1][0], a01.y, bq.x); ffma2(acc[1][1], a01.y, bq.y);
            ffma2(acc[2][0], a23.x, bq.x); ffma2(acc[2][1], a23.x, bq.y);
            ffma2(acc[3][0], a23.y, bq.x); ffma2(acc[3][1], a23.y, bq.y);
        }
        __syncthreads();
    }
    #pragma unroll
    for (int i = 0; i < 4; i++) {
        int m = m0 + ty * 4 + i;
        #pragma unroll
        for (int j = 0; j < 2; j++) {
            float lo, hi; upk2(acc[i][j], lo, hi);
            int n = tx * 4 + j * 2;
            out[(size_t)m * 64 + n]     = lo + bias[n];
            out[(size_t)m * 64 + n + 1] = hi + bias[n + 1];
        }
    }
}

// ---------------- forecast = FSEQ @ fore_W + fore_b ----------------
__global__ __launch_bounds__(256) void forecast_kernel(
    const float* __restrict__ Wf, const float* __restrict__ bf, float* __restrict__ out)
{
    __shared__ __align__(16) float rows[8][256];
    int tid = threadIdx.x;
    int m0 = blockIdx.x * 8;
    #pragma unroll
    for (int i = 0; i < 8; i++) {
        int flat = tid + 256 * i;
        int r = flat >> 8, cc = flat & 255;
        rows[r][cc] = d_FSEQ[(size_t)(m0 + r) * 256 + cc];
    }
    __syncthreads();
    int r = tid >> 5, n = tid & 31;
    float acc = bf[n];
    #pragma unroll 8
    for (int k = 0; k < 256; k++) acc += rows[r][k] * Wf[k * 32 + n];
    out[(size_t)(m0 + r) * 32 + n] = acc;
}

// ---------------- launch ----------------
extern "C" void kernel_launch(void* const* d_in, const int* in_sizes, int n_in,
                              void* d_out, int out_size)
{
    const float* inputs = (const float*)d_in[0];
    const float* conv_k = (const float*)d_in[1];
    const float* conv_b = (const float*)d_in[2];
    const float* enc_W  = (const float*)d_in[3];
    const float* enc_U  = (const float*)d_in[4];
    const float* enc_b  = (const float*)d_in[5];
    const float* cell_W = (const float*)d_in[6];
    const float* cell_U = (const float*)d_in[7];
    const float* cell_b = (const float*)d_in[8];
    const float* fore_W = (const float*)d_in[9];
    const float* fore_b = (const float*)d_in[10];
    const float* back_W = (const float*)d_in[11];
    const float* back_b = (const float*)d_in[12];
    float* out = (float*)d_out;

    const int conv_smem = (136 * CAP + 64 * ZBP) * 4;      // 55424 B
    const int rec_smem  = (32 * HP + 4 * 32 * RP) * 4;     // 70656 B
    cudaFuncSetAttribute(conv_tf32,
                         cudaFuncAttributeMaxDynamicSharedMemorySize, conv_smem);
    cudaFuncSetAttribute(lstm_persistent,
                         cudaFuncAttributeMaxDynamicSharedMemorySize, rec_smem);

    conv_tf32<<<dim3(4, BATCH * 4), 256, conv_smem>>>(inputs, conv_k, conv_b);     // idx 0
    gemm_zx_tf32<<<dim3(G4 / 64, (BATCH * SEQL) / 128), 256>>>(enc_W, enc_b);      // idx 1
    pad_kernel<<<1, 32>>>();                                                       // idx 2
    lstm_persistent<<<NCTA_REC, 256, rec_smem>>>(enc_U, cell_W, cell_U, cell_b);   // idx 3 (ncu slot)
    forecast_kernel<<<(BATCH * OUTSTEPS) / 8, 256>>>(fore_W, fore_b, out);
    gemm_back_kernel<<<(BATCH * SEQL) / 64, 256>>>(back_W, back_b,
                                                   out + (size_t)BATCH * OUTSTEPS * OUTDIMS);
}

// round 16
// speedup vs baseline: 1.9967x; 1.0392x over previous
#include <cuda_runtime.h>
#include <cstdint>
#include <math.h>

#define BATCH    256
#define SEQL     512
#define INDIM    64
#define UNITS    256
#define OUTSTEPS 64
#define OUTDIMS  32
#define G4       1024   // 4 * UNITS
#define NCTA_REC 128
#define HP       264    // hT row pitch (floats)
#define RP2      136    // red row pitch (128 cols + 8 pad)
#define ZAP      20     // ZX gemm A smem pitch
#define ZBP      72     // B smem pitch (ZX + conv)
#define CAP      68     // conv A smem pitch

typedef unsigned long long ull;

// ---------------- scratch (static device globals; no allocation) ----------------
__device__ float d_X[BATCH * SEQL * UNITS];            // conv output
__device__ float d_ZX[(size_t)SEQL * BATCH * G4];      // x@W + b, [t][b][1024]
__device__ float d_HSEQ[BATCH * SEQL * UNITS];         // encoder hidden seq
__device__ float d_FSEQ[BATCH * OUTSTEPS * UNITS];     // decoder hidden seq
__device__ float d_HX[2][BATCH * UNITS];               // ping-pong h, tf32 bits
__device__ unsigned g_cnt2[16][32];                     // per-batch-group barrier (padded lines)
__device__ unsigned g_gen2[16][32];

// ---------------- f32x2 helpers (backcast) ----------------
__device__ __forceinline__ ull pk2(float lo, float hi) {
    ull r; asm("mov.b64 %0, {%1, %2};" : "=l"(r) : "f"(lo), "f"(hi)); return r;
}
__device__ __forceinline__ void upk2(ull v, float& lo, float& hi) {
    asm("mov.b64 {%0, %1}, %2;" : "=f"(lo), "=f"(hi) : "l"(v));
}
__device__ __forceinline__ void ffma2(ull& d, ull a, ull b) {
    asm("fma.rn.f32x2 %0, %1, %2, %0;" : "+l"(d) : "l"(a), "l"(b));
}

// tf32 + mma helpers
__device__ __forceinline__ uint32_t to_tf32(float x) {
    uint32_t r; asm("cvt.rna.tf32.f32 %0, %1;" : "=r"(r) : "f"(x)); return r;
}
__device__ __forceinline__ void mma_tf32(float* c,
    uint32_t a0, uint32_t a1, uint32_t a2, uint32_t a3, uint32_t b0, uint32_t b1)
{
    asm("mma.sync.aligned.m16n8k8.row.col.f32.tf32.tf32.f32 "
        "{%0,%1,%2,%3}, {%4,%5,%6,%7}, {%8,%9}, {%0,%1,%2,%3};"
        : "+f"(c[0]), "+f"(c[1]), "+f"(c[2]), "+f"(c[3])
        : "r"(a0), "r"(a1), "r"(a2), "r"(a3), "r"(b0), "r"(b1));
}

// fast, overflow-safe gate functions
__device__ __forceinline__ float fast_sigmoid(float x) {
    return __fdividef(1.f, 1.f + __expf(-x));
}
__device__ __forceinline__ float fast_tanh(float x) {
    float e = __expf(-2.f * fabsf(x));
    float t = __fdividef(1.f - e, 1.f + e);
    return copysignf(t, x);
}

// ---------------- conv1d 'same' (K=5) + bias + relu via tf32 MMA ----------------
__global__ __launch_bounds__(256) void conv_tf32(
    const float* __restrict__ in, const float* __restrict__ ck, const float* __restrict__ cb)
{
    extern __shared__ uint32_t csm[];
    uint32_t* As = csm;                    // 136*CAP
    uint32_t* Bs = csm + 136 * CAP;        // 64*ZBP

    int tid = threadIdx.x;
    int w = tid >> 5, lane = tid & 31;
    int r4 = lane >> 2, t4 = lane & 3;
    int wm = w >> 1, wn = w & 1;           // warp grid 4(M) x 2(N)
    int n0 = blockIdx.x * 64;
    int by = blockIdx.y;
    int b  = by >> 2;
    int l0 = (by & 3) * 128;

    #pragma unroll
    for (int i = 0; i < 9; i++) {
        int flat = tid + 256 * i;
        if (flat < 132 * 16) {
            int r = flat >> 4, c4 = (flat & 15) * 4;
            int l = l0 - 2 + r;
            float4 v = make_float4(0.f, 0.f, 0.f, 0.f);
            if (l >= 0 && l < SEQL)
                v = *(const float4*)&in[((size_t)b * SEQL + l) * INDIM + c4];
            uint32_t* dst = &As[r * CAP + c4];
            dst[0] = to_tf32(v.x); dst[1] = to_tf32(v.y);
            dst[2] = to_tf32(v.z); dst[3] = to_tf32(v.w);
        }
    }

    float c[2][4][4];
    #pragma unroll
    for (int mt = 0; mt < 2; mt++)
        #pragma unroll
        for (int nt = 0; nt < 4; nt++)
            #pragma unroll
            for (int i = 0; i < 4; i++) c[mt][nt][i] = 0.f;

    for (int tap = 0; tap < 5; tap++) {
        __syncthreads();
        #pragma unroll
        for (int i = 0; i < 4; i++) {
            int flat = tid + 256 * i;
            int k = flat >> 4, c4 = (flat & 15) * 4;
            float4 v = *(const float4*)&ck[((size_t)(tap * 64 + k)) * 256 + n0 + c4];
            uint32_t* dst = &Bs[k * ZBP + c4];
            dst[0] = to_tf32(v.x); dst[1] = to_tf32(v.y);
            dst[2] = to_tf32(v.z); dst[3] = to_tf32(v.w);
        }
        __syncthreads();
        #pragma unroll
        for (int k8 = 0; k8 < 64; k8 += 8) {
            uint32_t a[2][4];
            #pragma unroll
            for (int mt = 0; mt < 2; mt++) {
                int rb = wm * 32 + mt * 16 + tap;
                a[mt][0] = As[(rb + r4) * CAP + k8 + t4];
                a[mt][1] = As[(rb + r4 + 8) * CAP + k8 + t4];
                a[mt][2] = As[(rb + r4) * CAP + k8 + t4 + 4];
                a[mt][3] = As[(rb + r4 + 8) * CAP + k8 + t4 + 4];
            }
            #pragma unroll
            for (int nt = 0; nt < 4; nt++) {
                int coln = wn * 32 + nt * 8 + r4;
                uint32_t b0 = Bs[(k8 + t4) * ZBP + coln];
                uint32_t b1 = Bs[(k8 + t4 + 4) * ZBP + coln];
                mma_tf32(c[0][nt], a[0][0], a[0][1], a[0][2], a[0][3], b0, b1);
                mma_tf32(c[1][nt], a[1][0], a[1][1], a[1][2], a[1][3], b0, b1);
            }
        }
    }

    #pragma unroll
    for (int mt = 0; mt < 2; mt++) {
        #pragma unroll
        for (int nt = 0; nt < 4; nt++) {
            int col = n0 + wn * 32 + nt * 8 + 2 * t4;
            float b0 = __ldg(&cb[col]), b1 = __ldg(&cb[col + 1]);
            int l1 = l0 + wm * 32 + mt * 16 + r4;
            *(float2*)&d_X[((size_t)b * SEQL + l1) * UNITS + col] =
                make_float2(fmaxf(c[mt][nt][0] + b0, 0.f), fmaxf(c[mt][nt][1] + b1, 0.f));
            int l2 = l1 + 8;
            *(float2*)&d_X[((size_t)b * SEQL + l2) * UNITS + col] =
                make_float2(fmaxf(c[mt][nt][2] + b0, 0.f), fmaxf(c[mt][nt][3] + b1, 0.f));
        }
    }
}

// ---------------- ZX = X @ enc_W + enc_b via tf32 MMA, register double-buffer ----------------
__global__ __launch_bounds__(256) void gemm_zx_tf32(
    const float* __restrict__ W, const float* __restrict__ bias)
{
    __shared__ uint32_t As[128 * ZAP];
    __shared__ uint32_t Bs[16 * ZBP];
    int tid = threadIdx.x;
    int w = tid >> 5, lane = tid & 31;
    int r4 = lane >> 2, t4 = lane & 3;
    int wm = w >> 1, wn = w & 1;
    int n0 = blockIdx.x * 64;
    int m0 = blockIdx.y * 128;

    int arow0 = tid >> 2,          ak0 = (tid & 3) * 4;
    int arow1 = (tid + 256) >> 2,  ak1 = ((tid + 256) & 3) * 4;
    int bk = tid >> 4, bc4 = (tid & 15) * 4;

    float c[2][4][4];
    #pragma unroll
    for (int mt = 0; mt < 2; mt++)
        #pragma unroll
        for (int nt = 0; nt < 4; nt++)
            #pragma unroll
            for (int i = 0; i < 4; i++) c[mt][nt][i] = 0.f;

    float4 avr0 = *(const float4*)&d_X[(size_t)(m0 + arow0) * 256 + ak0];
    float4 avr1 = *(const float4*)&d_X[(size_t)(m0 + arow1) * 256 + ak1];
    float4 bvr  = *(const float4*)&W[(size_t)bk * G4 + n0 + bc4];

    for (int k0 = 0; k0 < 256; k0 += 16) {
        {
            uint32_t* d0 = &As[arow0 * ZAP + ak0];
            d0[0] = to_tf32(avr0.x); d0[1] = to_tf32(avr0.y);
            d0[2] = to_tf32(avr0.z); d0[3] = to_tf32(avr0.w);
            uint32_t* d1 = &As[arow1 * ZAP + ak1];
            d1[0] = to_tf32(avr1.x); d1[1] = to_tf32(avr1.y);
            d1[2] = to_tf32(avr1.z); d1[3] = to_tf32(avr1.w);
            uint32_t* db = &Bs[bk * ZBP + bc4];
            db[0] = to_tf32(bvr.x); db[1] = to_tf32(bvr.y);
            db[2] = to_tf32(bvr.z); db[3] = to_tf32(bvr.w);
        }
        __syncthreads();

        if (k0 + 16 < 256) {
            int kn = k0 + 16;
            avr0 = *(const float4*)&d_X[(size_t)(m0 + arow0) * 256 + kn + ak0];
            avr1 = *(const float4*)&d_X[(size_t)(m0 + arow1) * 256 + kn + ak1];
            bvr  = *(const float4*)&W[(size_t)(kn + bk) * G4 + n0 + bc4];
        }

        #pragma unroll
        for (int k8 = 0; k8 < 16; k8 += 8) {
            uint32_t a[2][4];
            #pragma unroll
            for (int mt = 0; mt < 2; mt++) {
                int rb = wm * 32 + mt * 16;
                a[mt][0] = As[(rb + r4) * ZAP + k8 + t4];
                a[mt][1] = As[(rb + r4 + 8) * ZAP + k8 + t4];
                a[mt][2] = As[(rb + r4) * ZAP + k8 + t4 + 4];
                a[mt][3] = As[(rb + r4 + 8) * ZAP + k8 + t4 + 4];
            }
            #pragma unroll
            for (int nt = 0; nt < 4; nt++) {
                int coln = wn * 32 + nt * 8 + r4;
                uint32_t b0 = Bs[(k8 + t4) * ZBP + coln];
                uint32_t b1 = Bs[(k8 + t4 + 4) * ZBP + coln];
                mma_tf32(c[0][nt], a[0][0], a[0][1], a[0][2], a[0][3], b0, b1);
                mma_tf32(c[1][nt], a[1][0], a[1][1], a[1][2], a[1][3], b0, b1);
            }
        }
        __syncthreads();
    }
    #pragma unroll
    for (int mt = 0; mt < 2; mt++) {
        #pragma unroll
        for (int nt = 0; nt < 4; nt++) {
            int col = n0 + wn * 32 + nt * 8 + 2 * t4;
            float b0 = __ldg(&bias[col]), b1 = __ldg(&bias[col + 1]);
            int m_r = m0 + wm * 32 + mt * 16 + r4;
            int bi = m_r >> 9, tt = m_r & 511;
            *(float2*)&d_ZX[((size_t)tt * BATCH + bi) * G4 + col] =
                make_float2(c[mt][nt][0] + b0, c[mt][nt][1] + b1);
            int m_r2 = m_r + 8;
            int bi2 = m_r2 >> 9, tt2 = m_r2 & 511;
            *(float2*)&d_ZX[((size_t)tt2 * BATCH + bi2) * G4 + col] =
                make_float2(c[mt][nt][2] + b0, c[mt][nt][3] + b1);
        }
    }
}

// no-op pad so lstm_persistent stays at launch index 3 (ncu capture slot)
__global__ void pad_kernel() {}

// ---------------- per-batch-group barrier: 8 CTAs, own padded line (R12 algorithm) ----------------
__device__ __forceinline__ void group_sync(int bt) {
    __syncthreads();
    if (threadIdx.x == 0) {
        unsigned gen = *(volatile unsigned*)&g_gen2[bt][0];
        __threadfence();
        if (atomicAdd(&g_cnt2[bt][0], 1u) == 7) {
            *(volatile unsigned*)&g_cnt2[bt][0] = 0;
            __threadfence();
            atomicAdd(&g_gen2[bt][0], 1u);
        } else {
            while (*(volatile unsigned*)&g_gen2[bt][0] == gen) { }
        }
        __threadfence();
    }
    __syncthreads();
}

// ---------------- persistent LSTM: tf32 warp-MMA, split-k4, 8-CTA sync groups ----------------
// 128 CTAs x 256 threads. CTA = 32 units (128 gate cols) x 16 batches, K=256.
// 16 batch groups of 8 CTAs; sync scope = 8 (halved skew + arrive chain vs R12).
// Warp (kh = w>>1 k-quarter, ch = w&1 col-half of 64): 1 m-tile x 8 n-tiles x 8 k-iters
// = 64 HMMA/warp/step (identical to R12). Bf 128 regs (loaded once per phase).
__global__ __launch_bounds__(256, 1) void lstm_persistent(
    const float* __restrict__ encU, const float* __restrict__ cellW,
    const float* __restrict__ cellU, const float* __restrict__ cellB)
{
    extern __shared__ float smem_f[];
    float* hT  = smem_f;                 // 16*HP floats  (16896 B)
    float* red = smem_f + 16 * HP;       // 4*16*RP2 floats (34816 B)

    int tid  = threadIdx.x;
    int w    = tid >> 5;
    int lane = tid & 31;
    int r4 = lane >> 2;
    int t4 = lane & 3;
    int kh = w >> 1;             // 0..3  k-quarter
    int ch = w & 1;              // 0..1  col-half (64 cols each)
    int ct = blockIdx.x & 7;     // unit tile 0..7 (32 units)
    int bt = blockIdx.x >> 3;    // batch group 0..15 (16 batches)
    int u0 = ct * 32;
    int b0 = bt * 16;

    int guu = tid & 31;          // gate role: unit 0..31
    int gbl = tid >> 5;          // gate role: batch 0..7 (2 passes -> 16)
    int gu  = u0 + guu;

    // B-fragment G4 columns: CTA col c in 0..127 <-> gate g=c>>5, unit uu=c&31
    int bcol[8];
    #pragma unroll
    for (int nt = 0; nt < 8; nt++) {
        int col = ch * 64 + nt * 8 + r4;
        bcol[nt] = (col >> 5) * 256 + u0 + (col & 31);
    }

    // ---- encoder U -> B fragments (tf32), once ----
    uint32_t Bf[8][8][2];
    #pragma unroll
    for (int kk = 0; kk < 8; kk++) {
        int k = kh * 64 + kk * 8 + t4;
        #pragma unroll
        for (int nt = 0; nt < 8; nt++) {
            Bf[kk][nt][0] = to_tf32(__ldg(&encU[(size_t)k * G4 + bcol[nt]]));
            Bf[kk][nt][1] = to_tf32(__ldg(&encU[(size_t)(k + 4) * G4 + bcol[nt]]));
        }
    }

    float cst[2] = {0.f, 0.f};          // c state: batches gbl and gbl+8
    float bz[4]  = {0.f, 0.f, 0.f, 0.f};

    // ---- prefetch zini for t=0 ----
    float zini[2][4];
    #pragma unroll
    for (int p = 0; p < 2; p++) {
        const float* r = d_ZX + ((size_t)(b0 + p * 8 + gbl)) * G4 + gu;
        #pragma unroll
        for (int g = 0; g < 4; g++) zini[p][g] = __ldcg(r + g * 256);
    }

    #pragma unroll 1
    for (int s = 0; s < SEQL + OUTSTEPS; s++) {
        int dec = (s >= SEQL);
        int t = dec ? s - SEQL : s;

        if (s == SEQL) {   // decoder weights: cell_W + cell_U folded
            #pragma unroll
            for (int kk = 0; kk < 8; kk++) {
                int k = kh * 64 + kk * 8 + t4;
                #pragma unroll
                for (int nt = 0; nt < 8; nt++) {
                    size_t o0 = (size_t)k * G4 + bcol[nt];
                    size_t o1 = (size_t)(k + 4) * G4 + bcol[nt];
                    Bf[kk][nt][0] = to_tf32(__ldg(&cellW[o0]) + __ldg(&cellU[o0]));
                    Bf[kk][nt][1] = to_tf32(__ldg(&cellW[o1]) + __ldg(&cellU[o1]));
                }
            }
            #pragma unroll
            for (int g = 0; g < 4; g++) bz[g] = __ldg(cellB + g * 256 + gu);
        }

        // ---- stage h_prev (tf32 bits) from d_HX into hT[b][k] (16 batches) ----
        if (s == 0) {
            for (int idx = tid; idx < 16 * HP; idx += 256) hT[idx] = 0.f;
        } else {
            const float* hin = d_HX[s & 1];
            #pragma unroll
            for (int i = 0; i < 4; i++) {
                int flat = tid + 256 * i;
                int bl = flat >> 6;              // 0..15
                int k4 = (flat & 63) * 4;        // 0..252
                float4 v = __ldcg((const float4*)(hin + (size_t)(b0 + bl) * UNITS + k4));
                *(float4*)&hT[bl * HP + k4] = v;
            }
        }
        __syncthreads();

        // ---- z partial = h @ U over this warp's k-quarter (m=16, n=64) ----
        float c0[8][4];
        #pragma unroll
        for (int nt = 0; nt < 8; nt++)
            #pragma unroll
            for (int i = 0; i < 4; i++) c0[nt][i] = 0.f;

        #pragma unroll
        for (int kk = 0; kk < 8; kk++) {
            int k0 = kh * 64 + kk * 8 + t4;
            uint32_t a0 = __float_as_uint(hT[r4 * HP + k0]);
            uint32_t a1 = __float_as_uint(hT[(r4 + 8) * HP + k0]);
            uint32_t a2 = __float_as_uint(hT[r4 * HP + k0 + 4]);
            uint32_t a3 = __float_as_uint(hT[(r4 + 8) * HP + k0 + 4]);
            #pragma unroll
            for (int nt = 0; nt < 8; nt++)
                mma_tf32(c0[nt], a0, a1, a2, a3, Bf[kk][nt][0], Bf[kk][nt][1]);
        }

        // ---- scatter partials to red[kh][row][col] ----
        #pragma unroll
        for (int nt = 0; nt < 8; nt++) {
            int cb = ch * 64 + nt * 8 + 2 * t4;
            float* r0 = &red[(kh * 16 + r4) * RP2 + cb];
            r0[0] = c0[nt][0];
            r0[1] = c0[nt][1];
            float* r1 = &red[(kh * 16 + r4 + 8) * RP2 + cb];
            r1[0] = c0[nt][2];
            r1[1] = c0[nt][3];
        }
        __syncthreads();

        // ---- gates (thread = (guu, gbl)), batches gbl and gbl+8 ----
        float* hx = d_HX[(s + 1) & 1];
        #pragma unroll
        for (int p = 0; p < 2; p++) {
            int bl = p * 8 + gbl;
            float z[4];
            #pragma unroll
            for (int g = 0; g < 4; g++) {
                float acc = dec ? bz[g] : zini[p][g];
                #pragma unroll
                for (int q = 0; q < 4; q++)
                    acc += red[(q * 16 + bl) * RP2 + g * 32 + guu];
                z[g] = acc;
            }

            float ig = fast_sigmoid(z[0]);
            float fg = fast_sigmoid(z[1]);
            float gg = fast_tanh(z[2]);
            float og = fast_sigmoid(z[3]);
            float cn = fg * cst[p] + ig * gg;
            float hn = og * fast_tanh(cn);
            cst[p] = cn;

            int b = b0 + bl;
            if (!dec) d_HSEQ[((size_t)b * SEQL + t) * UNITS + gu] = hn;
            else      d_FSEQ[((size_t)b * OUTSTEPS + t) * UNITS + gu] = hn;
            hx[(size_t)b * UNITS + gu] = __uint_as_float(to_tf32(hn));
        }

        // ---- prefetch next encoder step's zini (hidden under barrier) ----
        if (s + 1 < SEQL) {
            int tn = s + 1;
            #pragma unroll
            for (int p = 0; p < 2; p++) {
                const float* r = d_ZX + ((size_t)tn * BATCH + b0 + p * 8 + gbl) * G4 + gu;
                #pragma unroll
                for (int g = 0; g < 4; g++) zini[p][g] = __ldcg(r + g * 256);
            }
        }

        group_sync(bt);
    }
}

// ---------------- backcast = HSEQ @ back_W + back_b (M=131072, N=64, K=256), f32x2 ----------------
__global__ __launch_bounds__(256) void gemm_back_kernel(
    const float* __restrict__ Bw, const float* __restrict__ bias, float* __restrict__ out)
{
    __shared__ __align__(16) ull   As2[16 * 64];
    __shared__ __align__(16) float Bs [16 * 64];
    int tid = threadIdx.x;
    int m0 = blockIdx.x * 64;
    int tx = tid & 15, ty = tid >> 4;
    ull acc[4][2];
    #pragma unroll
    for (int i = 0; i < 4; i++) { acc[i][0] = 0ull; acc[i][1] = 0ull; }
    int lam = tid >> 2, lak = (tid & 3) * 4;
    int lbk = tid >> 4, lbn = (tid & 15) * 4;
    for (int k0 = 0; k0 < 256; k0 += 16) {
        float4 av = *(const float4*)&d_HSEQ[(size_t)(m0 + lam) * 256 + k0 + lak];
        float4 bv = *(const float4*)&Bw[(size_t)(k0 + lbk) * 64 + lbn];
        As2[(lak + 0) * 64 + lam] = pk2(av.x, av.x);
        As2[(lak + 1) * 64 + lam] = pk2(av.y, av.y);
        As2[(lak + 2) * 64 + lam] = pk2(av.z, av.z);
        As2[(lak + 3) * 64 + lam] = pk2(av.w, av.w);
        *(float4*)&Bs[lbk * 64 + lbn] = bv;
        __syncthreads();
        #pragma unroll
        for (int k = 0; k < 16; k++) {
            ulonglong2 a01 = *(const ulonglong2*)&As2[k * 64 + ty * 4];
            ulonglong2 a23 = *(const ulonglong2*)&As2[k * 64 + ty * 4 + 2];
            ulonglong2 bq  = *(const ulonglong2*)&Bs[k * 64 + tx * 4];
            ffma2(acc[0][0], a01.x, bq.x); ffma2(acc[0][1], a01.x, bq.y);
            ffma2(acc[1][0], a01.y, bq.x); ffma2(acc[1][1], a01.y, bq.y);
            ffma2(acc[2][0], a23.x, bq.x); ffma2(acc[2][1], a23.x, bq.y);
            ffma2(acc[3][0], a23.y, bq.x); ffma2(acc[3][1], a23.y, bq.y);
        }
        __syncthreads();
    }
    #pragma unroll
    for (int i = 0; i < 4; i++) {
        int m = m0 + ty * 4 + i;
        #pragma unroll
        for (int j = 0; j < 2; j++) {
            float lo, hi; upk2(acc[i][j], lo, hi);
            int n = tx * 4 + j * 2;
            out[(size_t)m * 64 + n]     = lo + bias[n];
            out[(size_t)m * 64 + n + 1] = hi + bias[n + 1];
        }
    }
}

// ---------------- forecast = FSEQ @ fore_W + fore_b ----------------
__global__ __launch_bounds__(256) void forecast_kernel(
    const float* __restrict__ Wf, const float* __restrict__ bf, float* __restrict__ out)
{
    __shared__ __align__(16) float rows[8][256];
    int tid = threadIdx.x;
    int m0 = blockIdx.x * 8;
    #pragma unroll
    for (int i = 0; i < 8; i++) {
        int flat = tid + 256 * i;
        int r = flat >> 8, cc = flat & 255;
        rows[r][cc] = d_FSEQ[(size_t)(m0 + r) * 256 + cc];
    }
    __syncthreads();
    int r = tid >> 5, n = tid & 31;
    float acc = bf[n];
    #pragma unroll 8
    for (int k = 0; k < 256; k++) acc += rows[r][k] * Wf[k * 32 + n];
    out[(size_t)(m0 + r) * 32 + n] = acc;
}

// ---------------- launch ----------------
extern "C" void kernel_launch(void* const* d_in, const int* in_sizes, int n_in,
                              void* d_out, int out_size)
{
    const float* inputs = (const float*)d_in[0];
    const float* conv_k = (const float*)d_in[1];
    const float* conv_b = (const float*)d_in[2];
    const float* enc_W  = (const float*)d_in[3];
    const float* enc_U  = (const float*)d_in[4];
    const float* enc_b  = (const float*)d_in[5];
    const float* cell_W = (const float*)d_in[6];
    const float* cell_U = (const float*)d_in[7];
    const float* cell_b = (const float*)d_in[8];
    const float* fore_W = (const float*)d_in[9];
    const float* fore_b = (const float*)d_in[10];
    const float* back_W = (const float*)d_in[11];
    const float* back_b = (const float*)d_in[12];
    float* out = (float*)d_out;

    const int conv_smem = (136 * CAP + 64 * ZBP) * 4;      // 55424 B
    const int rec_smem  = (16 * HP + 4 * 16 * RP2) * 4;    // 51712 B
    cudaFuncSetAttribute(conv_tf32,
                         cudaFuncAttributeMaxDynamicSharedMemorySize, conv_smem);
    cudaFuncSetAttribute(lstm_persistent,
                         cudaFuncAttributeMaxDynamicSharedMemorySize, rec_smem);

    conv_tf32<<<dim3(4, BATCH * 4), 256, conv_smem>>>(inputs, conv_k, conv_b);     // idx 0
    gemm_zx_tf32<<<dim3(G4 / 64, (BATCH * SEQL) / 128), 256>>>(enc_W, enc_b);      // idx 1
    pad_kernel<<<1, 32>>>();                                                       // idx 2
    lstm_persistent<<<NCTA_REC, 256, rec_smem>>>(enc_U, cell_W, cell_U, cell_b);   // idx 3 (ncu slot)
    forecast_kernel<<<(BATCH * OUTSTEPS) / 8, 256>>>(fore_W, fore_b, out);
    gemm_back_kernel<<<(BATCH * SEQL) / 64, 256>>>(back_W, back_b,
                                                   out + (size_t)BATCH * OUTSTEPS * OUTDIMS);
}

// round 17
// speedup vs baseline: 2.0219x; 1.0126x over previous
#include <cuda_runtime.h>
#include <cstdint>
#include <math.h>

#define BATCH    256
#define SEQL     512
#define INDIM    64
#define UNITS    256
#define OUTSTEPS 64
#define OUTDIMS  32
#define G4       1024   // 4 * UNITS
#define NCTA_REC 128
#define HP       264    // hT row pitch (floats)
#define RP2      136    // red row pitch (128 cols + 8 pad)
#define ZAP      20     // ZX gemm A smem pitch
#define ZBP      72     // B smem pitch (ZX + conv)
#define CAP      68     // conv A smem pitch

typedef unsigned long long ull;

// ---------------- scratch (static device globals; no allocation) ----------------
__device__ float d_X[BATCH * SEQL * UNITS];            // conv output
__device__ float d_ZX[(size_t)SEQL * BATCH * G4];      // x@W + b, [t][b][1024]
__device__ float d_HSEQ[BATCH * SEQL * UNITS];         // encoder hidden seq (per-step slots)
__device__ float d_FSEQ[BATCH * OUTSTEPS * UNITS];     // decoder hidden seq (per-step slots)
__device__ unsigned g_flag[16][32];                     // per-group flags: [bt][ct<8], 128B/group

// ---------------- f32x2 helpers (backcast) ----------------
__device__ __forceinline__ ull pk2(float lo, float hi) {
    ull r; asm("mov.b64 %0, {%1, %2};" : "=l"(r) : "f"(lo), "f"(hi)); return r;
}
__device__ __forceinline__ void upk2(ull v, float& lo, float& hi) {
    asm("mov.b64 {%0, %1}, %2;" : "=f"(lo), "=f"(hi) : "l"(v));
}
__device__ __forceinline__ void ffma2(ull& d, ull a, ull b) {
    asm("fma.rn.f32x2 %0, %1, %2, %0;" : "+l"(d) : "l"(a), "l"(b));
}

// tf32 + mma helpers
__device__ __forceinline__ uint32_t to_tf32(float x) {
    uint32_t r; asm("cvt.rna.tf32.f32 %0, %1;" : "=r"(r) : "f"(x)); return r;
}
__device__ __forceinline__ void mma_tf32(float* c,
    uint32_t a0, uint32_t a1, uint32_t a2, uint32_t a3, uint32_t b0, uint32_t b1)
{
    asm("mma.sync.aligned.m16n8k8.row.col.f32.tf32.tf32.f32 "
        "{%0,%1,%2,%3}, {%4,%5,%6,%7}, {%8,%9}, {%0,%1,%2,%3};"
        : "+f"(c[0]), "+f"(c[1]), "+f"(c[2]), "+f"(c[3])
        : "r"(a0), "r"(a1), "r"(a2), "r"(a3), "r"(b0), "r"(b1));
}

// fast, overflow-safe gate functions
__device__ __forceinline__ float fast_sigmoid(float x) {
    return __fdividef(1.f, 1.f + __expf(-x));
}
__device__ __forceinline__ float fast_tanh(float x) {
    float e = __expf(-2.f * fabsf(x));
    float t = __fdividef(1.f - e, 1.f + e);
    return copysignf(t, x);
}

// ---------------- conv1d 'same' (K=5) + bias + relu via tf32 MMA ----------------
__global__ __launch_bounds__(256) void conv_tf32(
    const float* __restrict__ in, const float* __restrict__ ck, const float* __restrict__ cb)
{
    extern __shared__ uint32_t csm[];
    uint32_t* As = csm;                    // 136*CAP
    uint32_t* Bs = csm + 136 * CAP;        // 64*ZBP

    int tid = threadIdx.x;
    int w = tid >> 5, lane = tid & 31;
    int r4 = lane >> 2, t4 = lane & 3;
    int wm = w >> 1, wn = w & 1;           // warp grid 4(M) x 2(N)
    int n0 = blockIdx.x * 64;
    int by = blockIdx.y;
    int b  = by >> 2;
    int l0 = (by & 3) * 128;

    #pragma unroll
    for (int i = 0; i < 9; i++) {
        int flat = tid + 256 * i;
        if (flat < 132 * 16) {
            int r = flat >> 4, c4 = (flat & 15) * 4;
            int l = l0 - 2 + r;
            float4 v = make_float4(0.f, 0.f, 0.f, 0.f);
            if (l >= 0 && l < SEQL)
                v = *(const float4*)&in[((size_t)b * SEQL + l) * INDIM + c4];
            uint32_t* dst = &As[r * CAP + c4];
            dst[0] = to_tf32(v.x); dst[1] = to_tf32(v.y);
            dst[2] = to_tf32(v.z); dst[3] = to_tf32(v.w);
        }
    }

    float c[2][4][4];
    #pragma unroll
    for (int mt = 0; mt < 2; mt++)
        #pragma unroll
        for (int nt = 0; nt < 4; nt++)
            #pragma unroll
            for (int i = 0; i < 4; i++) c[mt][nt][i] = 0.f;

    for (int tap = 0; tap < 5; tap++) {
        __syncthreads();
        #pragma unroll
        for (int i = 0; i < 4; i++) {
            int flat = tid + 256 * i;
            int k = flat >> 4, c4 = (flat & 15) * 4;
            float4 v = *(const float4*)&ck[((size_t)(tap * 64 + k)) * 256 + n0 + c4];
            uint32_t* dst = &Bs[k * ZBP + c4];
            dst[0] = to_tf32(v.x); dst[1] = to_tf32(v.y);
            dst[2] = to_tf32(v.z); dst[3] = to_tf32(v.w);
        }
        __syncthreads();
        #pragma unroll
        for (int k8 = 0; k8 < 64; k8 += 8) {
            uint32_t a[2][4];
            #pragma unroll
            for (int mt = 0; mt < 2; mt++) {
                int rb = wm * 32 + mt * 16 + tap;
                a[mt][0] = As[(rb + r4) * CAP + k8 + t4];
                a[mt][1] = As[(rb + r4 + 8) * CAP + k8 + t4];
                a[mt][2] = As[(rb + r4) * CAP + k8 + t4 + 4];
                a[mt][3] = As[(rb + r4 + 8) * CAP + k8 + t4 + 4];
            }
            #pragma unroll
            for (int nt = 0; nt < 4; nt++) {
                int coln = wn * 32 + nt * 8 + r4;
                uint32_t b0 = Bs[(k8 + t4) * ZBP + coln];
                uint32_t b1 = Bs[(k8 + t4 + 4) * ZBP + coln];
                mma_tf32(c[0][nt], a[0][0], a[0][1], a[0][2], a[0][3], b0, b1);
                mma_tf32(c[1][nt], a[1][0], a[1][1], a[1][2], a[1][3], b0, b1);
            }
        }
    }

    #pragma unroll
    for (int mt = 0; mt < 2; mt++) {
        #pragma unroll
        for (int nt = 0; nt < 4; nt++) {
            int col = n0 + wn * 32 + nt * 8 + 2 * t4;
            float b0 = __ldg(&cb[col]), b1 = __ldg(&cb[col + 1]);
            int l1 = l0 + wm * 32 + mt * 16 + r4;
            *(float2*)&d_X[((size_t)b * SEQL + l1) * UNITS + col] =
                make_float2(fmaxf(c[mt][nt][0] + b0, 0.f), fmaxf(c[mt][nt][1] + b1, 0.f));
            int l2 = l1 + 8;
            *(float2*)&d_X[((size_t)b * SEQL + l2) * UNITS + col] =
                make_float2(fmaxf(c[mt][nt][2] + b0, 0.f), fmaxf(c[mt][nt][3] + b1, 0.f));
        }
    }
}

// ---------------- ZX = X @ enc_W + enc_b via tf32 MMA, register double-buffer ----------------
__global__ __launch_bounds__(256) void gemm_zx_tf32(
    const float* __restrict__ W, const float* __restrict__ bias)
{
    __shared__ uint32_t As[128 * ZAP];
    __shared__ uint32_t Bs[16 * ZBP];
    int tid = threadIdx.x;
    int w = tid >> 5, lane = tid & 31;
    int r4 = lane >> 2, t4 = lane & 3;
    int wm = w >> 1, wn = w & 1;
    int n0 = blockIdx.x * 64;
    int m0 = blockIdx.y * 128;

    int arow0 = tid >> 2,          ak0 = (tid & 3) * 4;
    int arow1 = (tid + 256) >> 2,  ak1 = ((tid + 256) & 3) * 4;
    int bk = tid >> 4, bc4 = (tid & 15) * 4;

    float c[2][4][4];
    #pragma unroll
    for (int mt = 0; mt < 2; mt++)
        #pragma unroll
        for (int nt = 0; nt < 4; nt++)
            #pragma unroll
            for (int i = 0; i < 4; i++) c[mt][nt][i] = 0.f;

    float4 avr0 = *(const float4*)&d_X[(size_t)(m0 + arow0) * 256 + ak0];
    float4 avr1 = *(const float4*)&d_X[(size_t)(m0 + arow1) * 256 + ak1];
    float4 bvr  = *(const float4*)&W[(size_t)bk * G4 + n0 + bc4];

    for (int k0 = 0; k0 < 256; k0 += 16) {
        {
            uint32_t* d0 = &As[arow0 * ZAP + ak0];
            d0[0] = to_tf32(avr0.x); d0[1] = to_tf32(avr0.y);
            d0[2] = to_tf32(avr0.z); d0[3] = to_tf32(avr0.w);
            uint32_t* d1 = &As[arow1 * ZAP + ak1];
            d1[0] = to_tf32(avr1.x); d1[1] = to_tf32(avr1.y);
            d1[2] = to_tf32(avr1.z); d1[3] = to_tf32(avr1.w);
            uint32_t* db = &Bs[bk * ZBP + bc4];
            db[0] = to_tf32(bvr.x); db[1] = to_tf32(bvr.y);
            db[2] = to_tf32(bvr.z); db[3] = to_tf32(bvr.w);
        }
        __syncthreads();

        if (k0 + 16 < 256) {
            int kn = k0 + 16;
            avr0 = *(const float4*)&d_X[(size_t)(m0 + arow0) * 256 + kn + ak0];
            avr1 = *(const float4*)&d_X[(size_t)(m0 + arow1) * 256 + kn + ak1];
            bvr  = *(const float4*)&W[(size_t)(kn + bk) * G4 + n0 + bc4];
        }

        #pragma unroll
        for (int k8 = 0; k8 < 16; k8 += 8) {
            uint32_t a[2][4];
            #pragma unroll
            for (int mt = 0; mt < 2; mt++) {
                int rb = wm * 32 + mt * 16;
                a[mt][0] = As[(rb + r4) * ZAP + k8 + t4];
                a[mt][1] = As[(rb + r4 + 8) * ZAP + k8 + t4];
                a[mt][2] = As[(rb + r4) * ZAP + k8 + t4 + 4];
                a[mt][3] = As[(rb + r4 + 8) * ZAP + k8 + t4 + 4];
            }
            #pragma unroll
            for (int nt = 0; nt < 4; nt++) {
                int coln = wn * 32 + nt * 8 + r4;
                uint32_t b0 = Bs[(k8 + t4) * ZBP + coln];
                uint32_t b1 = Bs[(k8 + t4 + 4) * ZBP + coln];
                mma_tf32(c[0][nt], a[0][0], a[0][1], a[0][2], a[0][3], b0, b1);
                mma_tf32(c[1][nt], a[1][0], a[1][1], a[1][2], a[1][3], b0, b1);
            }
        }
        __syncthreads();
    }
    #pragma unroll
    for (int mt = 0; mt < 2; mt++) {
        #pragma unroll
        for (int nt = 0; nt < 4; nt++) {
            int col = n0 + wn * 32 + nt * 8 + 2 * t4;
            float b0 = __ldg(&bias[col]), b1 = __ldg(&bias[col + 1]);
            int m_r = m0 + wm * 32 + mt * 16 + r4;
            int bi = m_r >> 9, tt = m_r & 511;
            *(float2*)&d_ZX[((size_t)tt * BATCH + bi) * G4 + col] =
                make_float2(c[mt][nt][0] + b0, c[mt][nt][1] + b1);
            int m_r2 = m_r + 8;
            int bi2 = m_r2 >> 9, tt2 = m_r2 & 511;
            *(float2*)&d_ZX[((size_t)tt2 * BATCH + bi2) * G4 + col] =
                make_float2(c[mt][nt][2] + b0, c[mt][nt][3] + b1);
        }
    }
}

// zero the barrier flags each launch (graph-replay safe); keeps lstm at launch idx 3
__global__ void zero_flags_kernel() {
    int i = threadIdx.x;
    if (i < 512) ((unsigned*)g_flag)[i] = 0;
}

// ---------------- monotonic flag barrier: 8 parallel arrivals, 1-thread 1-sector poll ----------------
__device__ __forceinline__ void group_arrive(int bt, int ct, unsigned val) {
    __syncthreads();                          // CTA's h stores done
    if (threadIdx.x == 0) {
        __threadfence();                      // release (cumulative for CTA)
        *(volatile unsigned*)&g_flag[bt][ct] = val;
    }
}
__device__ __forceinline__ void group_wait(int bt, unsigned val) {
    if (threadIdx.x == 0) {
        volatile unsigned* f = &g_flag[bt][0];
        for (;;) {
            bool ok = true;
            #pragma unroll
            for (int i = 0; i < 8; i++) ok &= (f[i] >= val);
            if (ok) break;
        }
        __threadfence();                      // acquire
    }
    __syncthreads();
}

// ---------------- persistent LSTM: tf32 warp-MMA, split-k4, 8-CTA groups, flag barrier ----------------
// 128 CTAs x 256 threads. CTA = 32 units (128 gate cols) x 16 batches, K=256.
// h exchanged through per-timestep HSEQ/FSEQ slots (no ping-pong, no WAR hazard);
// staging converts fp32 -> tf32 on load (numerically identical to producer-side cvt).
__global__ __launch_bounds__(256, 1) void lstm_persistent(
    const float* __restrict__ encU, const float* __restrict__ cellW,
    const float* __restrict__ cellU, const float* __restrict__ cellB)
{
    extern __shared__ float smem_f[];
    float* hT  = smem_f;                 // 16*HP floats  (16896 B)
    float* red = smem_f + 16 * HP;       // 4*16*RP2 floats (34816 B)

    int tid  = threadIdx.x;
    int w    = tid >> 5;
    int lane = tid & 31;
    int r4 = lane >> 2;
    int t4 = lane & 3;
    int kh = w >> 1;             // 0..3  k-quarter
    int ch = w & 1;              // 0..1  col-half (64 cols each)
    int ct = blockIdx.x & 7;     // unit tile 0..7 (32 units)
    int bt = blockIdx.x >> 3;    // batch group 0..15 (16 batches)
    int u0 = ct * 32;
    int b0 = bt * 16;

    int guu = tid & 31;          // gate role: unit 0..31
    int gbl = tid >> 5;          // gate role: batch 0..7 (2 passes -> 16)
    int gu  = u0 + guu;

    int bcol[8];
    #pragma unroll
    for (int nt = 0; nt < 8; nt++) {
        int col = ch * 64 + nt * 8 + r4;
        bcol[nt] = (col >> 5) * 256 + u0 + (col & 31);
    }

    // ---- encoder U -> B fragments (tf32), once ----
    uint32_t Bf[8][8][2];
    #pragma unroll
    for (int kk = 0; kk < 8; kk++) {
        int k = kh * 64 + kk * 8 + t4;
        #pragma unroll
        for (int nt = 0; nt < 8; nt++) {
            Bf[kk][nt][0] = to_tf32(__ldg(&encU[(size_t)k * G4 + bcol[nt]]));
            Bf[kk][nt][1] = to_tf32(__ldg(&encU[(size_t)(k + 4) * G4 + bcol[nt]]));
        }
    }

    float cst[2] = {0.f, 0.f};          // c state: batches gbl and gbl+8
    float bz[4]  = {0.f, 0.f, 0.f, 0.f};

    // ---- prefetch zini for t=0 ----
    float zini[2][4];
    #pragma unroll
    for (int p = 0; p < 2; p++) {
        const float* r = d_ZX + ((size_t)(b0 + p * 8 + gbl)) * G4 + gu;
        #pragma unroll
        for (int g = 0; g < 4; g++) zini[p][g] = __ldcg(r + g * 256);
    }

    #pragma unroll 1
    for (int s = 0; s < SEQL + OUTSTEPS; s++) {
        int dec = (s >= SEQL);
        int t = dec ? s - SEQL : s;

        if (s == SEQL) {   // decoder weights: cell_W + cell_U folded
            #pragma unroll
            for (int kk = 0; kk < 8; kk++) {
                int k = kh * 64 + kk * 8 + t4;
                #pragma unroll
                for (int nt = 0; nt < 8; nt++) {
                    size_t o0 = (size_t)k * G4 + bcol[nt];
                    size_t o1 = (size_t)(k + 4) * G4 + bcol[nt];
                    Bf[kk][nt][0] = to_tf32(__ldg(&cellW[o0]) + __ldg(&cellU[o0]));
                    Bf[kk][nt][1] = to_tf32(__ldg(&cellW[o1]) + __ldg(&cellU[o1]));
                }
            }
            #pragma unroll
            for (int g = 0; g < 4; g++) bz[g] = __ldg(cellB + g * 256 + gu);
        }

        // ---- wait for all 8 producers of h(s-1), then stage into hT (cvt to tf32) ----
        if (s > 0) group_wait(bt, (unsigned)s);

        if (s == 0) {
            for (int idx = tid; idx < 16 * HP; idx += 256) hT[idx] = 0.f;
        } else {
            #pragma unroll
            for (int i = 0; i < 4; i++) {
                int flat = tid + 256 * i;
                int bl = flat >> 6;              // 0..15
                int k4 = (flat & 63) * 4;        // 0..252
                int b = b0 + bl;
                float4 v;
                if (s <= SEQL)
                    v = __ldcg((const float4*)(d_HSEQ + ((size_t)b * SEQL + (s - 1)) * UNITS + k4));
                else
                    v = __ldcg((const float4*)(d_FSEQ + ((size_t)b * OUTSTEPS + (s - 1 - SEQL)) * UNITS + k4));
                float* dst = &hT[bl * HP + k4];
                dst[0] = __uint_as_float(to_tf32(v.x));
                dst[1] = __uint_as_float(to_tf32(v.y));
                dst[2] = __uint_as_float(to_tf32(v.z));
                dst[3] = __uint_as_float(to_tf32(v.w));
            }
        }
        __syncthreads();

        // ---- z partial = h @ U over this warp's k-quarter (m=16, n=64) ----
        float c0[8][4];
        #pragma unroll
        for (int nt = 0; nt < 8; nt++)
            #pragma unroll
            for (int i = 0; i < 4; i++) c0[nt][i] = 0.f;

        #pragma unroll
        for (int kk = 0; kk < 8; kk++) {
            int k0 = kh * 64 + kk * 8 + t4;
            uint32_t a0 = __float_as_uint(hT[r4 * HP + k0]);
            uint32_t a1 = __float_as_uint(hT[(r4 + 8) * HP + k0]);
            uint32_t a2 = __float_as_uint(hT[r4 * HP + k0 + 4]);
            uint32_t a3 = __float_as_uint(hT[(r4 + 8) * HP + k0 + 4]);
            #pragma unroll
            for (int nt = 0; nt < 8; nt++)
                mma_tf32(c0[nt], a0, a1, a2, a3, Bf[kk][nt][0], Bf[kk][nt][1]);
        }

        // ---- scatter partials to red[kh][row][col] ----
        #pragma unroll
        for (int nt = 0; nt < 8; nt++) {
            int cb = ch * 64 + nt * 8 + 2 * t4;
            float* r0 = &red[(kh * 16 + r4) * RP2 + cb];
            r0[0] = c0[nt][0];
            r0[1] = c0[nt][1];
            float* r1 = &red[(kh * 16 + r4 + 8) * RP2 + cb];
            r1[0] = c0[nt][2];
            r1[1] = c0[nt][3];
        }
        __syncthreads();

        // ---- gates (thread = (guu, gbl)), batches gbl and gbl+8 ----
        #pragma unroll
        for (int p = 0; p < 2; p++) {
            int bl = p * 8 + gbl;
            float z[4];
            #pragma unroll
            for (int g = 0; g < 4; g++) {
                float acc = dec ? bz[g] : zini[p][g];
                #pragma unroll
                for (int q = 0; q < 4; q++)
                    acc += red[(q * 16 + bl) * RP2 + g * 32 + guu];
                z[g] = acc;
            }

            float ig = fast_sigmoid(z[0]);
            float fg = fast_sigmoid(z[1]);
            float gg = fast_tanh(z[2]);
            float og = fast_sigmoid(z[3]);
            float cn = fg * cst[p] + ig * gg;
            float hn = og * fast_tanh(cn);
            cst[p] = cn;

            int b = b0 + bl;
            if (!dec) d_HSEQ[((size_t)b * SEQL + t) * UNITS + gu] = hn;
            else      d_FSEQ[((size_t)b * OUTSTEPS + t) * UNITS + gu] = hn;
        }

        // ---- prefetch next encoder step's zini (hidden under arrive/wait) ----
        if (s + 1 < SEQL) {
            int tn = s + 1;
            #pragma unroll
            for (int p = 0; p < 2; p++) {
                const float* r = d_ZX + ((size_t)tn * BATCH + b0 + p * 8 + gbl) * G4 + gu;
                #pragma unroll
                for (int g = 0; g < 4; g++) zini[p][g] = __ldcg(r + g * 256);
            }
        }

        group_arrive(bt, ct, (unsigned)(s + 1));
    }
}

// ---------------- backcast = HSEQ @ back_W + back_b (M=131072, N=64, K=256), f32x2 ----------------
__global__ __launch_bounds__(256) void gemm_back_kernel(
    const float* __restrict__ Bw, const float* __restrict__ bias, float* __restrict__ out)
{
    __shared__ __align__(16) ull   As2[16 * 64];
    __shared__ __align__(16) float Bs [16 * 64];
    int tid = threadIdx.x;
    int m0 = blockIdx.x * 64;
    int tx = tid & 15, ty = tid >> 4;
    ull acc[4][2];
    #pragma unroll
    for (int i = 0; i < 4; i++) { acc[i][0] = 0ull; acc[i][1] = 0ull; }
    int lam = tid >> 2, lak = (tid & 3) * 4;
    int lbk = tid >> 4, lbn = (tid & 15) * 4;
    for (int k0 = 0; k0 < 256; k0 += 16) {
        float4 av = *(const float4*)&d_HSEQ[(size_t)(m0 + lam) * 256 + k0 + lak];
        float4 bv = *(const float4*)&Bw[(size_t)(k0 + lbk) * 64 + lbn];
        As2[(lak + 0) * 64 + lam] = pk2(av.x, av.x);
        As2[(lak + 1) * 64 + lam] = pk2(av.y, av.y);
        As2[(lak + 2) * 64 + lam] = pk2(av.z, av.z);
        As2[(lak + 3) * 64 + lam] = pk2(av.w, av.w);
        *(float4*)&Bs[lbk * 64 + lbn] = bv;
        __syncthreads();
        #pragma unroll
        for (int k = 0; k < 16; k++) {
            ulonglong2 a01 = *(const ulonglong2*)&As2[k * 64 + ty * 4];
            ulonglong2 a23 = *(const ulonglong2*)&As2[k * 64 + ty * 4 + 2];
            ulonglong2 bq  = *(const ulonglong2*)&Bs[k * 64 + tx * 4];
            ffma2(acc[0][0], a01.x, bq.x); ffma2(acc[0][1], a01.x, bq.y);
            ffma2(acc[1][0], a01.y, bq.x); ffma2(acc[1][1], a01.y, bq.y);
            ffma2(acc[2][0], a23.x, bq.x); ffma2(acc[2][1], a23.x, bq.y);
            ffma2(acc[3][0], a23.y, bq.x); ffma2(acc[3][1], a23.y, bq.y);
        }
        __syncthreads();
    }
    #pragma unroll
    for (int i = 0; i < 4; i++) {
        int m = m0 + ty * 4 + i;
        #pragma unroll
        for (int j = 0; j < 2; j++) {
            float lo, hi; upk2(acc[i][j], lo, hi);
            int n = tx * 4 + j * 2;
            out[(size_t)m * 64 + n]     = lo + bias[n];
            out[(size_t)m * 64 + n + 1] = hi + bias[n + 1];
        }
    }
}

// ---------------- forecast = FSEQ @ fore_W + fore_b ----------------
__global__ __launch_bounds__(256) void forecast_kernel(
    const float* __restrict__ Wf, const float* __restrict__ bf, float* __restrict__ out)
{
    __shared__ __align__(16) float rows[8][256];
    int tid = threadIdx.x;
    int m0 = blockIdx.x * 8;
    #pragma unroll
    for (int i = 0; i < 8; i++) {
        int flat = tid + 256 * i;
        int r = flat >> 8, cc = flat & 255;
        rows[r][cc] = d_FSEQ[(size_t)(m0 + r) * 256 + cc];
    }
    __syncthreads();
    int r = tid >> 5, n = tid & 31;
    float acc = bf[n];
    #pragma unroll 8
    for (int k = 0; k < 256; k++) acc += rows[r][k] * Wf[k * 32 + n];
    out[(size_t)(m0 + r) * 32 + n] = acc;
}

// ---------------- launch ----------------
extern "C" void kernel_launch(void* const* d_in, const int* in_sizes, int n_in,
                              void* d_out, int out_size)
{
    const float* inputs = (const float*)d_in[0];
    const float* conv_k = (const float*)d_in[1];
    const float* conv_b = (const float*)d_in[2];
    const float* enc_W  = (const float*)d_in[3];
    const float* enc_U  = (const float*)d_in[4];
    const float* enc_b  = (const float*)d_in[5];
    const float* cell_W = (const float*)d_in[6];
    const float* cell_U = (const float*)d_in[7];
    const float* cell_b = (const float*)d_in[8];
    const float* fore_W = (const float*)d_in[9];
    const float* fore_b = (const float*)d_in[10];
    const float* back_W = (const float*)d_in[11];
    const float* back_b = (const float*)d_in[12];
    float* out = (float*)d_out;

    const int conv_smem = (136 * CAP + 64 * ZBP) * 4;      // 55424 B
    const int rec_smem  = (16 * HP + 4 * 16 * RP2) * 4;    // 51712 B
    cudaFuncSetAttribute(conv_tf32,
                         cudaFuncAttributeMaxDynamicSharedMemorySize, conv_smem);
    cudaFuncSetAttribute(lstm_persistent,
                         cudaFuncAttributeMaxDynamicSharedMemorySize, rec_smem);

    conv_tf32<<<dim3(4, BATCH * 4), 256, conv_smem>>>(inputs, conv_k, conv_b);     // idx 0
    gemm_zx_tf32<<<dim3(G4 / 64, (BATCH * SEQL) / 128), 256>>>(enc_W, enc_b);      // idx 1
    zero_flags_kernel<<<1, 512>>>();                                               // idx 2
    lstm_persistent<<<NCTA_REC, 256, rec_smem>>>(enc_U, cell_W, cell_U, cell_b);   // idx 3 (ncu slot)
    forecast_kernel<<<(BATCH * OUTSTEPS) / 8, 256>>>(fore_W, fore_b, out);
    gemm_back_kernel<<<(BATCH * SEQL) / 64, 256>>>(back_W, back_b,
                                                   out + (size_t)BATCH * OUTSTEPS * OUTDIMS);
}